// round 1
// baseline (speedup 1.0000x reference)
#include <cuda_runtime.h>
#include <cstdint>

#define B_ 8
#define C_ 256
#define N_ 4096
#define K_ 64

// Scratch for projection outputs (allowed: __device__ globals, no runtime alloc)
__device__ float g_F[(size_t)B_ * N_ * K_];   // [B][N][K]  8 MB
__device__ float g_G[(size_t)B_ * N_ * K_];   // [B][N][K]  8 MB
__device__ float g_H[(size_t)B_ * N_ * C_];   // [B][N][C] 32 MB

// ---------------- packed f32x2 helpers (Blackwell-only PTX) ----------------
__device__ __forceinline__ unsigned long long ffma2(unsigned long long a,
                                                    unsigned long long b,
                                                    unsigned long long c) {
    unsigned long long d;
    asm("fma.rn.f32x2 %0, %1, %2, %3;" : "=l"(d) : "l"(a), "l"(b), "l"(c));
    return d;
}
__device__ __forceinline__ unsigned long long pack2(float x) {
    unsigned long long r;
    unsigned int xi = __float_as_uint(x);
    asm("mov.b64 %0, {%1, %1};" : "=l"(r) : "r"(xi));
    return r;
}
__device__ __forceinline__ float2 unpack2(unsigned long long v) {
    unsigned int lo, hi;
    asm("mov.b64 {%0, %1}, %2;" : "=r"(lo), "=r"(hi) : "l"(v));
    return make_float2(__uint_as_float(lo), __uint_as_float(hi));
}

// ---------------------------------------------------------------------------
// Projection kernel: rows 0..63 -> WF, 64..127 -> WG, 128..383 -> WH.
// Each block: 128 n-values, 32 output rows. W slice staged transposed in smem
// (pad 36 floats -> 16B-aligned vector reads, modest store conflicts only once).
// ---------------------------------------------------------------------------
__global__ __launch_bounds__(128) void proj_kernel(
    const float* __restrict__ feat,
    const float* __restrict__ WF,
    const float* __restrict__ WG,
    const float* __restrict__ WH)
{
    __shared__ float sW[256 * 36];
    const int rg = blockIdx.y;
    const int b  = blockIdx.z;

    const float* W;
    float* dst;
    int r0, ld;
    if (rg < 2)      { W = WF; dst = g_F; r0 = rg * 32;       ld = K_; }
    else if (rg < 4) { W = WG; dst = g_G; r0 = (rg - 2) * 32; ld = K_; }
    else             { W = WH; dst = g_H; r0 = (rg - 4) * 32; ld = C_; }

    // stage W[r0..r0+31][0..255] transposed: sW[c*36 + r]
    for (int i = threadIdx.x; i < 32 * 256; i += 128) {
        int r = i >> 8, c = i & 255;
        sW[c * 36 + r] = W[(size_t)(r0 + r) * C_ + c];
    }
    __syncthreads();

    const int n = blockIdx.x * 128 + threadIdx.x;
    const float* fb = feat + (size_t)b * C_ * N_;

    unsigned long long acc2[16];
#pragma unroll
    for (int i = 0; i < 16; i++) acc2[i] = 0ULL;

#pragma unroll 4
    for (int c = 0; c < C_; c++) {
        float x = __ldg(fb + (size_t)c * N_ + n);     // coalesced over threads
        unsigned long long x2 = pack2(x);
        const ulonglong2* wv = (const ulonglong2*)(sW + c * 36);  // broadcast
#pragma unroll
        for (int r = 0; r < 8; r++) {
            ulonglong2 w = wv[r];
            acc2[2 * r]     = ffma2(x2, w.x, acc2[2 * r]);
            acc2[2 * r + 1] = ffma2(x2, w.y, acc2[2 * r + 1]);
        }
    }

    ulonglong2* drow = (ulonglong2*)(dst + ((size_t)b * N_ + n) * ld + r0);
#pragma unroll
    for (int r = 0; r < 8; r++) {
        ulonglong2 v;
        v.x = acc2[2 * r];
        v.y = acc2[2 * r + 1];
        drow[r] = v;
    }
}

// ---------------------------------------------------------------------------
// Flash-attention kernel. Block = 64 query rows (n) x full C=256 output dim.
// Thread (n = tid&63, q = tid>>6) owns d in [q*64, q*64+64) as 32 f32x2 accs.
// Streams 64 key tiles of 64; online softmax; epilogue fuses gamma*o + input
// (raw-reshape semantics => flat [B,N,C] layout == output [B,C,N] layout).
// ---------------------------------------------------------------------------
#define SG_OFF  (64 * 64)               // after sF
#define SS_OFF  (SG_OFF + 64 * 68)      // sG padded to 68 (16B-aligned rows)
#define SH_OFF  (SS_OFF + 64 * 65)      // sS padded to 65 (conflict-free scalar)
#define SMEM_FLOATS (SH_OFF + 64 * 256)
#define SMEM_BYTES  (SMEM_FLOATS * 4)   // 115968 B
#define LOG2E 1.4426950408889634f

__global__ __launch_bounds__(256) void attn_kernel(
    const float* __restrict__ input,
    const float* __restrict__ gamma_p,
    float* __restrict__ out)
{
    extern __shared__ float sm[];
    float* sF = sm;             // [64][64]   F tile (m, k)
    float* sG = sm + SG_OFF;    // [64][68]   G tile (n, k)
    float* sS = sm + SS_OFF;    // [64][65]   scores (n, m)
    float* sH = sm + SH_OFF;    // [64][256]  H tile (m, d)

    const int tid = threadIdx.x;
    const int n   = tid & 63;
    const int q   = tid >> 6;
    const int n0  = blockIdx.x * 64;
    const int b   = blockIdx.y;

    // Load this block's G tile once
    const float4* Gg = (const float4*)(g_G + ((size_t)b * N_ + n0) * K_);
    for (int i = tid; i < 64 * 16; i += 256) {
        int nn = i >> 4, k4 = i & 15;
        ((float4*)(sG + nn * 68))[k4] = Gg[i];
    }

    const float gm = __ldg(gamma_p);

    unsigned long long acc2[32];
#pragma unroll
    for (int i = 0; i < 32; i++) acc2[i] = 0ULL;
    float mrow = __int_as_float(0xff800000);   // -inf
    float lrow = 0.0f;

    const float4* Fg = (const float4*)(g_F + (size_t)b * N_ * K_);
    const float4* Hg = (const float4*)(g_H + (size_t)b * N_ * C_);

    for (int t = 0; t < N_ / 64; t++) {
        const int m0 = t * 64;
        __syncthreads();   // previous tile fully consumed (also guards sG @ t=0)

        // stage F tile [64m x 64k] and H tile [64m x 256d]
        for (int i = tid; i < 64 * 16; i += 256) {
            int mm = i >> 4, k4 = i & 15;
            ((float4*)(sF + mm * 64))[k4] = Fg[(size_t)(m0 + mm) * 16 + k4];
        }
        for (int i = tid; i < 64 * 64; i += 256) {
            int mm = i >> 6, d4 = i & 63;
            ((float4*)(sH + mm * 256))[d4] = Hg[(size_t)(m0 + mm) * 64 + d4];
        }
        __syncthreads();

        // ---- S = G(n,:) . F(m,:)^T  (thread computes its 16-m slice) ----
        const int mb = q * 16;
        unsigned long long s2[16];
#pragma unroll
        for (int i = 0; i < 16; i++) s2[i] = 0ULL;
        const ulonglong2* gp2 = (const ulonglong2*)(sG + n * 68);
#pragma unroll 4
        for (int k4 = 0; k4 < 16; k4++) {
            ulonglong2 g2 = gp2[k4];                      // conflict-free (pad 68)
#pragma unroll
            for (int mm = 0; mm < 16; mm++) {
                ulonglong2 f2 = ((const ulonglong2*)(sF + (mb + mm) * 64))[k4]; // broadcast
                s2[mm] = ffma2(g2.x, f2.x, s2[mm]);
                s2[mm] = ffma2(g2.y, f2.y, s2[mm]);
            }
        }
#pragma unroll
        for (int mm = 0; mm < 16; mm++) {
            float2 v = unpack2(s2[mm]);
            sS[n * 65 + mb + mm] = v.x + v.y;
        }
        __syncthreads();

        // ---- online softmax + PV (q-redundant row stats, consistent) ----
        const float* srow = sS + n * 65;
        float tmax = srow[0];
#pragma unroll
        for (int m = 1; m < 64; m++) tmax = fmaxf(tmax, srow[m]);
        float mnew = fmaxf(mrow, tmax);
        float corr = exp2f((mrow - mnew) * LOG2E);
        mrow = mnew;
        lrow *= corr;
        unsigned long long c2 = pack2(corr);
#pragma unroll
        for (int i = 0; i < 32; i++) acc2[i] = ffma2(acc2[i], c2, 0ULL);

#pragma unroll 2
        for (int m = 0; m < 64; m++) {
            float p = exp2f((srow[m] - mnew) * LOG2E);
            lrow += p;
            unsigned long long p2 = pack2(p);
            const ulonglong2* hp = (const ulonglong2*)(sH + m * 256 + q * 64); // broadcast
#pragma unroll
            for (int j = 0; j < 16; j++) {
                ulonglong2 hv = hp[j];
                acc2[2 * j]     = ffma2(p2, hv.x, acc2[2 * j]);
                acc2[2 * j + 1] = ffma2(p2, hv.y, acc2[2 * j + 1]);
            }
        }
    }

    // ---- epilogue: out = gamma * (acc/l) + input  (flat [B,N,C] layout) ----
    const float inv = 1.0f / lrow;
    const size_t base = ((size_t)b * N_ + (n0 + n)) * C_ + q * 64;
    const float4* iv4 = (const float4*)(input + base);
    float4* ov4 = (float4*)(out + base);
#pragma unroll
    for (int j = 0; j < 16; j++) {
        float2 a0 = unpack2(acc2[2 * j]);
        float2 a1 = unpack2(acc2[2 * j + 1]);
        float4 iv = iv4[j];
        float4 ov;
        ov.x = fmaf(gm, a0.x * inv, iv.x);
        ov.y = fmaf(gm, a0.y * inv, iv.y);
        ov.z = fmaf(gm, a1.x * inv, iv.z);
        ov.w = fmaf(gm, a1.y * inv, iv.w);
        ov4[j] = ov;
    }
}

// ---------------------------------------------------------------------------
extern "C" void kernel_launch(void* const* d_in, const int* in_sizes, int n_in,
                              void* d_out, int out_size) {
    (void)in_sizes; (void)n_in; (void)out_size;
    const float* input = (const float*)d_in[0];
    const float* feat  = (const float*)d_in[1];   // nms_feat
    const float* WF    = (const float*)d_in[2];
    const float* WG    = (const float*)d_in[3];
    const float* WH    = (const float*)d_in[4];
    const float* gamma = (const float*)d_in[5];
    float* out = (float*)d_out;

    cudaFuncSetAttribute(attn_kernel,
                         cudaFuncAttributeMaxDynamicSharedMemorySize, SMEM_BYTES);

    proj_kernel<<<dim3(N_ / 128, 12, B_), 128>>>(feat, WF, WG, WH);
    attn_kernel<<<dim3(N_ / 64, B_), 256, SMEM_BYTES>>>(input, gamma, out);
}

// round 2
// speedup vs baseline: 2.5411x; 2.5411x over previous
#include <cuda_runtime.h>
#include <cstdint>

#define B_ 8
#define C_ 256
#define N_ 4096
#define K_ 64
#define LOG2E 1.4426950408889634f

// Projection outputs, pre-split for error-compensated TF32 MMA.
__device__ float g_Fh[(size_t)B_ * N_ * K_];
__device__ float g_Fl[(size_t)B_ * N_ * K_];
__device__ float g_Gh[(size_t)B_ * N_ * K_];   // pre-scaled by log2(e)
__device__ float g_Gl[(size_t)B_ * N_ * K_];
__device__ float g_Ht[(size_t)B_ * N_ * C_];   // tf32-rounded

// ---------------- helpers ----------------
__device__ __forceinline__ uint32_t tf32_of(float x) {
    uint32_t r; asm("cvt.rna.tf32.f32 %0, %1;" : "=r"(r) : "f"(x)); return r;
}
__device__ __forceinline__ float ex2(float x) {
    float r; asm("ex2.approx.f32 %0, %1;" : "=f"(r) : "f"(x)); return r;
}
__device__ __forceinline__ void mma_tf32(float* c,
    uint32_t a0, uint32_t a1, uint32_t a2, uint32_t a3,
    uint32_t b0, uint32_t b1) {
    asm volatile("mma.sync.aligned.m16n8k8.row.col.f32.tf32.tf32.f32 "
        "{%0,%1,%2,%3},{%4,%5,%6,%7},{%8,%9},{%0,%1,%2,%3};"
        : "+f"(c[0]), "+f"(c[1]), "+f"(c[2]), "+f"(c[3])
        : "r"(a0), "r"(a1), "r"(a2), "r"(a3), "r"(b0), "r"(b1));
}
__device__ __forceinline__ unsigned long long ffma2(unsigned long long a,
                                                    unsigned long long b,
                                                    unsigned long long c) {
    unsigned long long d;
    asm("fma.rn.f32x2 %0, %1, %2, %3;" : "=l"(d) : "l"(a), "l"(b), "l"(c));
    return d;
}
__device__ __forceinline__ unsigned long long pack2(float x) {
    unsigned long long r;
    unsigned int xi = __float_as_uint(x);
    asm("mov.b64 %0, {%1, %1};" : "=l"(r) : "r"(xi));
    return r;
}
__device__ __forceinline__ float2 unpack2(unsigned long long v) {
    unsigned int lo, hi;
    asm("mov.b64 {%0, %1}, %2;" : "=r"(lo), "=r"(hi) : "l"(v));
    return make_float2(__uint_as_float(lo), __uint_as_float(hi));
}

// ---------------------------------------------------------------------------
// Projection: rg 0-1 -> F (hi/lo), 2-3 -> G (scaled by log2e, hi/lo),
//             4-11 -> H (tf32-rounded). 32 output rows per block.
// ---------------------------------------------------------------------------
__global__ __launch_bounds__(128) void proj_kernel(
    const float* __restrict__ feat,
    const float* __restrict__ WF,
    const float* __restrict__ WG,
    const float* __restrict__ WH)
{
    __shared__ float sW[256 * 36];
    const int rg = blockIdx.y;
    const int b  = blockIdx.z;

    const float* W;
    int r0, mode;                      // 0=F, 1=G, 2=H
    if (rg < 2)      { W = WF; r0 = rg * 32;       mode = 0; }
    else if (rg < 4) { W = WG; r0 = (rg - 2) * 32; mode = 1; }
    else             { W = WH; r0 = (rg - 4) * 32; mode = 2; }

    for (int i = threadIdx.x; i < 32 * 256; i += 128) {
        int r = i >> 8, c = i & 255;
        sW[c * 36 + r] = W[(size_t)(r0 + r) * C_ + c];
    }
    __syncthreads();

    const int n = blockIdx.x * 128 + threadIdx.x;
    const float* fb = feat + (size_t)b * C_ * N_;

    unsigned long long acc2[16];
#pragma unroll
    for (int i = 0; i < 16; i++) acc2[i] = 0ULL;

#pragma unroll 4
    for (int c = 0; c < C_; c++) {
        float x = __ldg(fb + (size_t)c * N_ + n);
        unsigned long long x2 = pack2(x);
        const ulonglong2* wv = (const ulonglong2*)(sW + c * 36);
#pragma unroll
        for (int r = 0; r < 8; r++) {
            ulonglong2 wq = wv[r];
            acc2[2 * r]     = ffma2(x2, wq.x, acc2[2 * r]);
            acc2[2 * r + 1] = ffma2(x2, wq.y, acc2[2 * r + 1]);
        }
    }

    float v[32];
#pragma unroll
    for (int i = 0; i < 16; i++) {
        float2 t = unpack2(acc2[i]);
        v[2 * i] = t.x; v[2 * i + 1] = t.y;
    }

    const size_t nb = (size_t)b * N_ + n;
    if (mode == 2) {
        float* dst = g_Ht + nb * C_ + r0;
#pragma unroll
        for (int j = 0; j < 8; j++) {
            float4 o;
            o.x = __uint_as_float(tf32_of(v[4 * j + 0]));
            o.y = __uint_as_float(tf32_of(v[4 * j + 1]));
            o.z = __uint_as_float(tf32_of(v[4 * j + 2]));
            o.w = __uint_as_float(tf32_of(v[4 * j + 3]));
            *(float4*)(dst + 4 * j) = o;
        }
    } else {
        const float scale = (mode == 1) ? LOG2E : 1.0f;
        float* dh = (mode == 1 ? g_Gh : g_Fh) + nb * K_ + r0;
        float* dl = (mode == 1 ? g_Gl : g_Fl) + nb * K_ + r0;
#pragma unroll
        for (int j = 0; j < 8; j++) {
            float4 h4, l4;
            float hv, xv;
#pragma unroll
            for (int e = 0; e < 4; e++) {
                xv = v[4 * j + e] * scale;
                hv = __uint_as_float(tf32_of(xv));
                ((float*)&h4)[e] = hv;
                ((float*)&l4)[e] = __uint_as_float(tf32_of(xv - hv));
            }
            *(float4*)(dh + 4 * j) = h4;
            *(float4*)(dl + 4 * j) = l4;
        }
    }
}

// ---------------------------------------------------------------------------
// TF32 flash attention. Block = 128 q-rows, 8 warps, each warp 16 rows x 256 d.
// m-tiles of 64. S = 3xTF32 (hi/lo G,F). PV = 2xTF32 (P split in regs, H tf32).
// S C-frags feed PV A-frags directly; column permutation folded into H B rows.
// ---------------------------------------------------------------------------
#define PADK 68
#define PADH 260
#define SGH 0
#define SGL (128 * PADK)
#define SFH (2 * 128 * PADK)
#define SFL (SFH + 64 * PADK)
#define SHH (SFL + 64 * PADK)
#define SMEMF (SHH + 64 * PADH)
#define SMEMB (SMEMF * 4)

__global__ __launch_bounds__(256, 1) void attn_kernel(
    const float* __restrict__ input,
    const float* __restrict__ gamma_p,
    float* __restrict__ out)
{
    extern __shared__ float sm[];
    const int tid  = threadIdx.x;
    const int lane = tid & 31;
    const int w    = tid >> 5;       // warp 0..7, owns rows [16w,16w+16)
    const int gr   = lane >> 2;      // group id 0..7
    const int tg   = lane & 3;       // thread-in-group 0..3
    const int n0   = blockIdx.x * 128;
    const int b    = blockIdx.y;

    // stage G tile (128 x 64, hi+lo) once
    {
        const float4* GH = (const float4*)(g_Gh + ((size_t)b * N_ + n0) * K_);
        const float4* GL = (const float4*)(g_Gl + ((size_t)b * N_ + n0) * K_);
        for (int i = tid; i < 128 * 16; i += 256) {
            int r = i >> 4, k4 = i & 15;
            *(float4*)(sm + SGH + r * PADK + k4 * 4) = GH[i];
            *(float4*)(sm + SGL + r * PADK + k4 * 4) = GL[i];
        }
    }

    float oacc[32][4];
#pragma unroll
    for (int i = 0; i < 32; i++) {
        oacc[i][0] = 0.f; oacc[i][1] = 0.f; oacc[i][2] = 0.f; oacc[i][3] = 0.f;
    }
    const float NEG_INF = __int_as_float(0xff800000);
    float mrow0 = NEG_INF, mrow1 = NEG_INF, lsum0 = 0.f, lsum1 = 0.f;

    const float4* FH = (const float4*)(g_Fh + (size_t)b * N_ * K_);
    const float4* FL = (const float4*)(g_Fl + (size_t)b * N_ * K_);
    const float4* HT = (const float4*)(g_Ht + (size_t)b * N_ * C_);

    const float* gh = sm + SGH + (w * 16 + gr) * PADK;
    const float* gl = sm + SGL + (w * 16 + gr) * PADK;

#pragma unroll 1
    for (int t = 0; t < N_ / 64; t++) {
        const int m0 = t * 64;
        __syncthreads();    // prior tile consumed (also covers sG staging @ t=0)

        for (int i = tid; i < 64 * 16; i += 256) {
            int r = i >> 4, k4 = i & 15;
            *(float4*)(sm + SFH + r * PADK + k4 * 4) = FH[(size_t)(m0 + r) * 16 + k4];
            *(float4*)(sm + SFL + r * PADK + k4 * 4) = FL[(size_t)(m0 + r) * 16 + k4];
        }
        for (int i = tid; i < 64 * 64; i += 256) {
            int r = i >> 6, d4 = i & 63;
            *(float4*)(sm + SHH + r * PADH + d4 * 4) = HT[(size_t)(m0 + r) * 64 + d4];
        }
        __syncthreads();

        // ---- S tile: sc[ms] = 16n x 8m C-frags, 3xTF32 ----
        float sc[8][4];
#pragma unroll
        for (int ms = 0; ms < 8; ms++) {
            sc[ms][0] = 0.f; sc[ms][1] = 0.f; sc[ms][2] = 0.f; sc[ms][3] = 0.f;
        }
#pragma unroll
        for (int kc = 0; kc < 8; kc++) {
            const int ko = kc * 8 + tg;
            uint32_t ah0 = __float_as_uint(gh[ko]);
            uint32_t ah1 = __float_as_uint(gh[8 * PADK + ko]);
            uint32_t ah2 = __float_as_uint(gh[ko + 4]);
            uint32_t ah3 = __float_as_uint(gh[8 * PADK + ko + 4]);
            uint32_t al0 = __float_as_uint(gl[ko]);
            uint32_t al1 = __float_as_uint(gl[8 * PADK + ko]);
            uint32_t al2 = __float_as_uint(gl[ko + 4]);
            uint32_t al3 = __float_as_uint(gl[8 * PADK + ko + 4]);
#pragma unroll
            for (int ms = 0; ms < 8; ms++) {
                const float* fh = sm + SFH + (ms * 8 + gr) * PADK + ko;
                const float* fl = sm + SFL + (ms * 8 + gr) * PADK + ko;
                uint32_t bh0 = __float_as_uint(fh[0]);
                uint32_t bh1 = __float_as_uint(fh[4]);
                uint32_t bl0 = __float_as_uint(fl[0]);
                uint32_t bl1 = __float_as_uint(fl[4]);
                mma_tf32(sc[ms], ah0, ah1, ah2, ah3, bh0, bh1);
                mma_tf32(sc[ms], ah0, ah1, ah2, ah3, bl0, bl1);
                mma_tf32(sc[ms], al0, al1, al2, al3, bh0, bh1);
            }
        }

        // ---- online softmax (logits already in log2 domain) ----
        float t0 = NEG_INF, t1 = NEG_INF;
#pragma unroll
        for (int ms = 0; ms < 8; ms++) {
            t0 = fmaxf(t0, fmaxf(sc[ms][0], sc[ms][1]));
            t1 = fmaxf(t1, fmaxf(sc[ms][2], sc[ms][3]));
        }
        t0 = fmaxf(t0, __shfl_xor_sync(0xffffffffu, t0, 1));
        t0 = fmaxf(t0, __shfl_xor_sync(0xffffffffu, t0, 2));
        t1 = fmaxf(t1, __shfl_xor_sync(0xffffffffu, t1, 1));
        t1 = fmaxf(t1, __shfl_xor_sync(0xffffffffu, t1, 2));

        const float mn0 = fmaxf(mrow0, t0);
        const float mn1 = fmaxf(mrow1, t1);
        const float cr0 = ex2(mrow0 - mn0);
        const float cr1 = ex2(mrow1 - mn1);
        mrow0 = mn0; mrow1 = mn1;
        lsum0 *= cr0; lsum1 *= cr1;
#pragma unroll
        for (int dt = 0; dt < 32; dt++) {
            oacc[dt][0] *= cr0; oacc[dt][1] *= cr0;
            oacc[dt][2] *= cr1; oacc[dt][3] *= cr1;
        }
#pragma unroll
        for (int ms = 0; ms < 8; ms++) {
            sc[ms][0] = ex2(sc[ms][0] - mn0);
            sc[ms][1] = ex2(sc[ms][1] - mn0);
            sc[ms][2] = ex2(sc[ms][2] - mn1);
            sc[ms][3] = ex2(sc[ms][3] - mn1);
            lsum0 += sc[ms][0] + sc[ms][1];
            lsum1 += sc[ms][2] + sc[ms][3];
        }

        // ---- PV: O += P * H, 2xTF32. C->A frag: a={c0,c2,c1,c3};
        //      A col k holds m=2k (k<4) / 2(k-4)+1, compensated in B rows. ----
#pragma unroll
        for (int mc = 0; mc < 8; mc++) {
            uint32_t ph0 = tf32_of(sc[mc][0]);
            uint32_t ph1 = tf32_of(sc[mc][2]);
            uint32_t ph2 = tf32_of(sc[mc][1]);
            uint32_t ph3 = tf32_of(sc[mc][3]);
            uint32_t pl0 = tf32_of(sc[mc][0] - __uint_as_float(ph0));
            uint32_t pl1 = tf32_of(sc[mc][2] - __uint_as_float(ph1));
            uint32_t pl2 = tf32_of(sc[mc][1] - __uint_as_float(ph2));
            uint32_t pl3 = tf32_of(sc[mc][3] - __uint_as_float(ph3));
            const float* hb = sm + SHH + (mc * 8 + 2 * tg) * PADH + gr;
#pragma unroll
            for (int dt = 0; dt < 32; dt++) {
                uint32_t b0 = __float_as_uint(hb[dt * 8]);
                uint32_t b1 = __float_as_uint(hb[PADH + dt * 8]);
                mma_tf32(oacc[dt], ph0, ph1, ph2, ph3, b0, b1);
                mma_tf32(oacc[dt], pl0, pl1, pl2, pl3, b0, b1);
            }
        }
    }

    // ---- epilogue: l reduce, out = gamma*(O/l) + input, flat [B,N,C] ----
    lsum0 += __shfl_xor_sync(0xffffffffu, lsum0, 1);
    lsum0 += __shfl_xor_sync(0xffffffffu, lsum0, 2);
    lsum1 += __shfl_xor_sync(0xffffffffu, lsum1, 1);
    lsum1 += __shfl_xor_sync(0xffffffffu, lsum1, 2);
    const float inv0 = 1.0f / lsum0;
    const float inv1 = 1.0f / lsum1;
    const float gm = __ldg(gamma_p);

    const int r0 = n0 + w * 16 + gr;
    const int r1 = r0 + 8;
    const size_t base0 = ((size_t)b * N_ + r0) * C_ + tg * 2;
    const size_t base1 = ((size_t)b * N_ + r1) * C_ + tg * 2;
#pragma unroll
    for (int dt = 0; dt < 32; dt++) {
        float2 iv0 = *(const float2*)(input + base0 + dt * 8);
        float2 iv1 = *(const float2*)(input + base1 + dt * 8);
        float2 ov0, ov1;
        ov0.x = fmaf(gm, oacc[dt][0] * inv0, iv0.x);
        ov0.y = fmaf(gm, oacc[dt][1] * inv0, iv0.y);
        ov1.x = fmaf(gm, oacc[dt][2] * inv1, iv1.x);
        ov1.y = fmaf(gm, oacc[dt][3] * inv1, iv1.y);
        *(float2*)(out + base0 + dt * 8) = ov0;
        *(float2*)(out + base1 + dt * 8) = ov1;
    }
}

// ---------------------------------------------------------------------------
extern "C" void kernel_launch(void* const* d_in, const int* in_sizes, int n_in,
                              void* d_out, int out_size) {
    (void)in_sizes; (void)n_in; (void)out_size;
    const float* input = (const float*)d_in[0];
    const float* feat  = (const float*)d_in[1];   // nms_feat
    const float* WF    = (const float*)d_in[2];
    const float* WG    = (const float*)d_in[3];
    const float* WH    = (const float*)d_in[4];
    const float* gamma = (const float*)d_in[5];
    float* out = (float*)d_out;

    cudaFuncSetAttribute(attn_kernel,
                         cudaFuncAttributeMaxDynamicSharedMemorySize, SMEMB);

    proj_kernel<<<dim3(N_ / 128, 12, B_), 128>>>(feat, WF, WG, WH);
    attn_kernel<<<dim3(N_ / 128, B_), 256, SMEMB>>>(input, gamma, out);
}

// round 3
// speedup vs baseline: 2.5430x; 1.0008x over previous
#include <cuda_runtime.h>
#include <cstdint>

#define B_ 8
#define C_ 256
#define N_ 4096
#define K_ 64
#define LOG2E 1.4426950408889634f

// Projection outputs, pre-split for error-compensated TF32 MMA.
__device__ float g_Fh[(size_t)B_ * N_ * K_];
__device__ float g_Fl[(size_t)B_ * N_ * K_];
__device__ float g_Gh[(size_t)B_ * N_ * K_];   // pre-scaled by log2(e)
__device__ float g_Gl[(size_t)B_ * N_ * K_];
__device__ float g_Ht[(size_t)B_ * N_ * C_];   // tf32-rounded

// ---------------- helpers ----------------
__device__ __forceinline__ uint32_t tf32_of(float x) {
    uint32_t r; asm("cvt.rna.tf32.f32 %0, %1;" : "=r"(r) : "f"(x)); return r;
}
__device__ __forceinline__ float ex2(float x) {
    float r; asm("ex2.approx.f32 %0, %1;" : "=f"(r) : "f"(x)); return r;
}
__device__ __forceinline__ void mma_tf32(float* c,
    uint32_t a0, uint32_t a1, uint32_t a2, uint32_t a3,
    uint32_t b0, uint32_t b1) {
    asm volatile("mma.sync.aligned.m16n8k8.row.col.f32.tf32.tf32.f32 "
        "{%0,%1,%2,%3},{%4,%5,%6,%7},{%8,%9},{%0,%1,%2,%3};"
        : "+f"(c[0]), "+f"(c[1]), "+f"(c[2]), "+f"(c[3])
        : "r"(a0), "r"(a1), "r"(a2), "r"(a3), "r"(b0), "r"(b1));
}
__device__ __forceinline__ unsigned long long ffma2(unsigned long long a,
                                                    unsigned long long b,
                                                    unsigned long long c) {
    unsigned long long d;
    asm("fma.rn.f32x2 %0, %1, %2, %3;" : "=l"(d) : "l"(a), "l"(b), "l"(c));
    return d;
}
__device__ __forceinline__ unsigned long long pack2(float x) {
    unsigned long long r;
    unsigned int xi = __float_as_uint(x);
    asm("mov.b64 %0, {%1, %1};" : "=l"(r) : "r"(xi));
    return r;
}
__device__ __forceinline__ float2 unpack2(unsigned long long v) {
    unsigned int lo, hi;
    asm("mov.b64 {%0, %1}, %2;" : "=r"(lo), "=r"(hi) : "l"(v));
    return make_float2(__uint_as_float(lo), __uint_as_float(hi));
}

// ---------------------------------------------------------------------------
// Projection: rg 0-1 -> F (hi/lo), 2-3 -> G (scaled by log2e, hi/lo),
//             4-11 -> H (tf32-rounded). 32 output rows per block.
// ---------------------------------------------------------------------------
__global__ __launch_bounds__(128) void proj_kernel(
    const float* __restrict__ feat,
    const float* __restrict__ WF,
    const float* __restrict__ WG,
    const float* __restrict__ WH)
{
    __shared__ float sW[256 * 36];
    const int rg = blockIdx.y;
    const int b  = blockIdx.z;

    const float* W;
    int r0, mode;                      // 0=F, 1=G, 2=H
    if (rg < 2)      { W = WF; r0 = rg * 32;       mode = 0; }
    else if (rg < 4) { W = WG; r0 = (rg - 2) * 32; mode = 1; }
    else             { W = WH; r0 = (rg - 4) * 32; mode = 2; }

    for (int i = threadIdx.x; i < 32 * 256; i += 128) {
        int r = i >> 8, c = i & 255;
        sW[c * 36 + r] = W[(size_t)(r0 + r) * C_ + c];
    }
    __syncthreads();

    const int n = blockIdx.x * 128 + threadIdx.x;
    const float* fb = feat + (size_t)b * C_ * N_;

    unsigned long long acc2[16];
#pragma unroll
    for (int i = 0; i < 16; i++) acc2[i] = 0ULL;

#pragma unroll 4
    for (int c = 0; c < C_; c++) {
        float x = __ldg(fb + (size_t)c * N_ + n);
        unsigned long long x2 = pack2(x);
        const ulonglong2* wv = (const ulonglong2*)(sW + c * 36);
#pragma unroll
        for (int r = 0; r < 8; r++) {
            ulonglong2 wq = wv[r];
            acc2[2 * r]     = ffma2(x2, wq.x, acc2[2 * r]);
            acc2[2 * r + 1] = ffma2(x2, wq.y, acc2[2 * r + 1]);
        }
    }

    float v[32];
#pragma unroll
    for (int i = 0; i < 16; i++) {
        float2 t = unpack2(acc2[i]);
        v[2 * i] = t.x; v[2 * i + 1] = t.y;
    }

    const size_t nb = (size_t)b * N_ + n;
    if (mode == 2) {
        float* dst = g_Ht + nb * C_ + r0;
#pragma unroll
        for (int j = 0; j < 8; j++) {
            float4 o;
            o.x = __uint_as_float(tf32_of(v[4 * j + 0]));
            o.y = __uint_as_float(tf32_of(v[4 * j + 1]));
            o.z = __uint_as_float(tf32_of(v[4 * j + 2]));
            o.w = __uint_as_float(tf32_of(v[4 * j + 3]));
            *(float4*)(dst + 4 * j) = o;
        }
    } else {
        const float scale = (mode == 1) ? LOG2E : 1.0f;
        float* dh = (mode == 1 ? g_Gh : g_Fh) + nb * K_ + r0;
        float* dl = (mode == 1 ? g_Gl : g_Fl) + nb * K_ + r0;
#pragma unroll
        for (int j = 0; j < 8; j++) {
            float4 h4, l4;
            float hv, xv;
#pragma unroll
            for (int e = 0; e < 4; e++) {
                xv = v[4 * j + e] * scale;
                hv = __uint_as_float(tf32_of(xv));
                ((float*)&h4)[e] = hv;
                ((float*)&l4)[e] = __uint_as_float(tf32_of(xv - hv));
            }
            *(float4*)(dh + 4 * j) = h4;
            *(float4*)(dl + 4 * j) = l4;
        }
    }
}

// ---------------------------------------------------------------------------
// TF32 flash attention. Block = 128 q-rows, 8 warps, each warp 16 rows x 256 d.
// m-tiles of 64. S = 3xTF32 (hi/lo G,F). PV = 2xTF32 (P split in regs, H tf32).
// S C-frags feed PV A-frags directly; column permutation folded into H B rows.
// ---------------------------------------------------------------------------
#define PADK 68
#define PADH 260
#define SGH 0
#define SGL (128 * PADK)
#define SFH (2 * 128 * PADK)
#define SFL (SFH + 64 * PADK)
#define SHH (SFL + 64 * PADK)
#define SMEMF (SHH + 64 * PADH)
#define SMEMB (SMEMF * 4)

__global__ __launch_bounds__(256, 1) void attn_kernel(
    const float* __restrict__ input,
    const float* __restrict__ gamma_p,
    float* __restrict__ out)
{
    extern __shared__ float sm[];
    const int tid  = threadIdx.x;
    const int lane = tid & 31;
    const int w    = tid >> 5;       // warp 0..7, owns rows [16w,16w+16)
    const int gr   = lane >> 2;      // group id 0..7
    const int tg   = lane & 3;       // thread-in-group 0..3
    const int n0   = blockIdx.x * 128;
    const int b    = blockIdx.y;

    // stage G tile (128 x 64, hi+lo) once
    {
        const float4* GH = (const float4*)(g_Gh + ((size_t)b * N_ + n0) * K_);
        const float4* GL = (const float4*)(g_Gl + ((size_t)b * N_ + n0) * K_);
        for (int i = tid; i < 128 * 16; i += 256) {
            int r = i >> 4, k4 = i & 15;
            *(float4*)(sm + SGH + r * PADK + k4 * 4) = GH[i];
            *(float4*)(sm + SGL + r * PADK + k4 * 4) = GL[i];
        }
    }

    float oacc[32][4];
#pragma unroll
    for (int i = 0; i < 32; i++) {
        oacc[i][0] = 0.f; oacc[i][1] = 0.f; oacc[i][2] = 0.f; oacc[i][3] = 0.f;
    }
    const float NEG_INF = __int_as_float(0xff800000);
    float mrow0 = NEG_INF, mrow1 = NEG_INF, lsum0 = 0.f, lsum1 = 0.f;

    const float4* FH = (const float4*)(g_Fh + (size_t)b * N_ * K_);
    const float4* FL = (const float4*)(g_Fl + (size_t)b * N_ * K_);
    const float4* HT = (const float4*)(g_Ht + (size_t)b * N_ * C_);

    const float* gh = sm + SGH + (w * 16 + gr) * PADK;
    const float* gl = sm + SGL + (w * 16 + gr) * PADK;

#pragma unroll 1
    for (int t = 0; t < N_ / 64; t++) {
        const int m0 = t * 64;
        __syncthreads();    // prior tile consumed (also covers sG staging @ t=0)

        for (int i = tid; i < 64 * 16; i += 256) {
            int r = i >> 4, k4 = i & 15;
            *(float4*)(sm + SFH + r * PADK + k4 * 4) = FH[(size_t)(m0 + r) * 16 + k4];
            *(float4*)(sm + SFL + r * PADK + k4 * 4) = FL[(size_t)(m0 + r) * 16 + k4];
        }
        for (int i = tid; i < 64 * 64; i += 256) {
            int r = i >> 6, d4 = i & 63;
            *(float4*)(sm + SHH + r * PADH + d4 * 4) = HT[(size_t)(m0 + r) * 64 + d4];
        }
        __syncthreads();

        // ---- S tile: sc[ms] = 16n x 8m C-frags, 3xTF32 ----
        float sc[8][4];
#pragma unroll
        for (int ms = 0; ms < 8; ms++) {
            sc[ms][0] = 0.f; sc[ms][1] = 0.f; sc[ms][2] = 0.f; sc[ms][3] = 0.f;
        }
#pragma unroll
        for (int kc = 0; kc < 8; kc++) {
            const int ko = kc * 8 + tg;
            uint32_t ah0 = __float_as_uint(gh[ko]);
            uint32_t ah1 = __float_as_uint(gh[8 * PADK + ko]);
            uint32_t ah2 = __float_as_uint(gh[ko + 4]);
            uint32_t ah3 = __float_as_uint(gh[8 * PADK + ko + 4]);
            uint32_t al0 = __float_as_uint(gl[ko]);
            uint32_t al1 = __float_as_uint(gl[8 * PADK + ko]);
            uint32_t al2 = __float_as_uint(gl[ko + 4]);
            uint32_t al3 = __float_as_uint(gl[8 * PADK + ko + 4]);
#pragma unroll
            for (int ms = 0; ms < 8; ms++) {
                const float* fh = sm + SFH + (ms * 8 + gr) * PADK + ko;
                const float* fl = sm + SFL + (ms * 8 + gr) * PADK + ko;
                uint32_t bh0 = __float_as_uint(fh[0]);
                uint32_t bh1 = __float_as_uint(fh[4]);
                uint32_t bl0 = __float_as_uint(fl[0]);
                uint32_t bl1 = __float_as_uint(fl[4]);
                mma_tf32(sc[ms], ah0, ah1, ah2, ah3, bh0, bh1);
                mma_tf32(sc[ms], ah0, ah1, ah2, ah3, bl0, bl1);
                mma_tf32(sc[ms], al0, al1, al2, al3, bh0, bh1);
            }
        }

        // ---- online softmax (logits already in log2 domain) ----
        float t0 = NEG_INF, t1 = NEG_INF;
#pragma unroll
        for (int ms = 0; ms < 8; ms++) {
            t0 = fmaxf(t0, fmaxf(sc[ms][0], sc[ms][1]));
            t1 = fmaxf(t1, fmaxf(sc[ms][2], sc[ms][3]));
        }
        t0 = fmaxf(t0, __shfl_xor_sync(0xffffffffu, t0, 1));
        t0 = fmaxf(t0, __shfl_xor_sync(0xffffffffu, t0, 2));
        t1 = fmaxf(t1, __shfl_xor_sync(0xffffffffu, t1, 1));
        t1 = fmaxf(t1, __shfl_xor_sync(0xffffffffu, t1, 2));

        const float mn0 = fmaxf(mrow0, t0);
        const float mn1 = fmaxf(mrow1, t1);
        const float cr0 = ex2(mrow0 - mn0);
        const float cr1 = ex2(mrow1 - mn1);
        mrow0 = mn0; mrow1 = mn1;
        lsum0 *= cr0; lsum1 *= cr1;
#pragma unroll
        for (int dt = 0; dt < 32; dt++) {
            oacc[dt][0] *= cr0; oacc[dt][1] *= cr0;
            oacc[dt][2] *= cr1; oacc[dt][3] *= cr1;
        }
#pragma unroll
        for (int ms = 0; ms < 8; ms++) {
            sc[ms][0] = ex2(sc[ms][0] - mn0);
            sc[ms][1] = ex2(sc[ms][1] - mn0);
            sc[ms][2] = ex2(sc[ms][2] - mn1);
            sc[ms][3] = ex2(sc[ms][3] - mn1);
            lsum0 += sc[ms][0] + sc[ms][1];
            lsum1 += sc[ms][2] + sc[ms][3];
        }

        // ---- PV: O += P * H, 2xTF32. C->A frag: a={c0,c2,c1,c3};
        //      A col k holds m=2k (k<4) / 2(k-4)+1, compensated in B rows. ----
#pragma unroll
        for (int mc = 0; mc < 8; mc++) {
            uint32_t ph0 = tf32_of(sc[mc][0]);
            uint32_t ph1 = tf32_of(sc[mc][2]);
            uint32_t ph2 = tf32_of(sc[mc][1]);
            uint32_t ph3 = tf32_of(sc[mc][3]);
            uint32_t pl0 = tf32_of(sc[mc][0] - __uint_as_float(ph0));
            uint32_t pl1 = tf32_of(sc[mc][2] - __uint_as_float(ph1));
            uint32_t pl2 = tf32_of(sc[mc][1] - __uint_as_float(ph2));
            uint32_t pl3 = tf32_of(sc[mc][3] - __uint_as_float(ph3));
            const float* hb = sm + SHH + (mc * 8 + 2 * tg) * PADH + gr;
#pragma unroll
            for (int dt = 0; dt < 32; dt++) {
                uint32_t b0 = __float_as_uint(hb[dt * 8]);
                uint32_t b1 = __float_as_uint(hb[PADH + dt * 8]);
                mma_tf32(oacc[dt], ph0, ph1, ph2, ph3, b0, b1);
                mma_tf32(oacc[dt], pl0, pl1, pl2, pl3, b0, b1);
            }
        }
    }

    // ---- epilogue: l reduce, out = gamma*(O/l) + input, flat [B,N,C] ----
    lsum0 += __shfl_xor_sync(0xffffffffu, lsum0, 1);
    lsum0 += __shfl_xor_sync(0xffffffffu, lsum0, 2);
    lsum1 += __shfl_xor_sync(0xffffffffu, lsum1, 1);
    lsum1 += __shfl_xor_sync(0xffffffffu, lsum1, 2);
    const float inv0 = 1.0f / lsum0;
    const float inv1 = 1.0f / lsum1;
    const float gm = __ldg(gamma_p);

    const int r0 = n0 + w * 16 + gr;
    const int r1 = r0 + 8;
    const size_t base0 = ((size_t)b * N_ + r0) * C_ + tg * 2;
    const size_t base1 = ((size_t)b * N_ + r1) * C_ + tg * 2;
#pragma unroll
    for (int dt = 0; dt < 32; dt++) {
        float2 iv0 = *(const float2*)(input + base0 + dt * 8);
        float2 iv1 = *(const float2*)(input + base1 + dt * 8);
        float2 ov0, ov1;
        ov0.x = fmaf(gm, oacc[dt][0] * inv0, iv0.x);
        ov0.y = fmaf(gm, oacc[dt][1] * inv0, iv0.y);
        ov1.x = fmaf(gm, oacc[dt][2] * inv1, iv1.x);
        ov1.y = fmaf(gm, oacc[dt][3] * inv1, iv1.y);
        *(float2*)(out + base0 + dt * 8) = ov0;
        *(float2*)(out + base1 + dt * 8) = ov1;
    }
}

// ---------------------------------------------------------------------------
extern "C" void kernel_launch(void* const* d_in, const int* in_sizes, int n_in,
                              void* d_out, int out_size) {
    (void)in_sizes; (void)n_in; (void)out_size;
    const float* input = (const float*)d_in[0];
    const float* feat  = (const float*)d_in[1];   // nms_feat
    const float* WF    = (const float*)d_in[2];
    const float* WG    = (const float*)d_in[3];
    const float* WH    = (const float*)d_in[4];
    const float* gamma = (const float*)d_in[5];
    float* out = (float*)d_out;

    cudaFuncSetAttribute(attn_kernel,
                         cudaFuncAttributeMaxDynamicSharedMemorySize, SMEMB);

    proj_kernel<<<dim3(N_ / 128, 12, B_), 128>>>(feat, WF, WG, WH);
    attn_kernel<<<dim3(N_ / 128, B_), 256, SMEMB>>>(input, gamma, out);
}

// round 4
// speedup vs baseline: 3.9215x; 1.5421x over previous
#include <cuda_runtime.h>
#include <cstdint>

#define B_ 8
#define C_ 256
#define N_ 4096
#define K_ 64
#define MT 32                       // m-tile rows (double-buffered)
#define LOG2E 1.4426950408889634f

// Projection outputs, pre-split for error-compensated TF32 MMA.
__device__ float g_Fh[(size_t)B_ * N_ * K_];
__device__ float g_Fl[(size_t)B_ * N_ * K_];
__device__ float g_Gh[(size_t)B_ * N_ * K_];   // pre-scaled by log2(e)
__device__ float g_Gl[(size_t)B_ * N_ * K_];
__device__ float g_Ht[(size_t)B_ * N_ * C_];   // tf32-rounded

// ---------------- helpers ----------------
__device__ __forceinline__ uint32_t tf32_of(float x) {
    uint32_t r; asm("cvt.rna.tf32.f32 %0, %1;" : "=r"(r) : "f"(x)); return r;
}
__device__ __forceinline__ float ex2(float x) {
    float r; asm("ex2.approx.f32 %0, %1;" : "=f"(r) : "f"(x)); return r;
}
__device__ __forceinline__ void mma_tf32(float* c,
    uint32_t a0, uint32_t a1, uint32_t a2, uint32_t a3,
    uint32_t b0, uint32_t b1) {
    asm volatile("mma.sync.aligned.m16n8k8.row.col.f32.tf32.tf32.f32 "
        "{%0,%1,%2,%3},{%4,%5,%6,%7},{%8,%9},{%0,%1,%2,%3};"
        : "+f"(c[0]), "+f"(c[1]), "+f"(c[2]), "+f"(c[3])
        : "r"(a0), "r"(a1), "r"(a2), "r"(a3), "r"(b0), "r"(b1));
}
__device__ __forceinline__ void cp16(uint32_t dst, const void* src) {
    asm volatile("cp.async.cg.shared.global [%0], [%1], 16;"
                 :: "r"(dst), "l"(src));
}
__device__ __forceinline__ void cp_commit() {
    asm volatile("cp.async.commit_group;");
}
__device__ __forceinline__ void cp_wait0() {
    asm volatile("cp.async.wait_group 0;");
}
__device__ __forceinline__ unsigned long long ffma2(unsigned long long a,
                                                    unsigned long long b,
                                                    unsigned long long c) {
    unsigned long long d;
    asm("fma.rn.f32x2 %0, %1, %2, %3;" : "=l"(d) : "l"(a), "l"(b), "l"(c));
    return d;
}
__device__ __forceinline__ unsigned long long pack2(float x) {
    unsigned long long r;
    unsigned int xi = __float_as_uint(x);
    asm("mov.b64 %0, {%1, %1};" : "=l"(r) : "r"(xi));
    return r;
}
__device__ __forceinline__ float2 unpack2(unsigned long long v) {
    unsigned int lo, hi;
    asm("mov.b64 {%0, %1}, %2;" : "=r"(lo), "=r"(hi) : "l"(v));
    return make_float2(__uint_as_float(lo), __uint_as_float(hi));
}

// ---------------------------------------------------------------------------
// Projection: rg 0-1 -> F (hi/lo), 2-3 -> G (scaled by log2e, hi/lo),
//             4-11 -> H (tf32-rounded). 32 output rows per block.
// ---------------------------------------------------------------------------
__global__ __launch_bounds__(128) void proj_kernel(
    const float* __restrict__ feat,
    const float* __restrict__ WF,
    const float* __restrict__ WG,
    const float* __restrict__ WH)
{
    __shared__ float sW[256 * 36];
    const int rg = blockIdx.y;
    const int b  = blockIdx.z;

    const float* W;
    int r0, mode;                      // 0=F, 1=G, 2=H
    if (rg < 2)      { W = WF; r0 = rg * 32;       mode = 0; }
    else if (rg < 4) { W = WG; r0 = (rg - 2) * 32; mode = 1; }
    else             { W = WH; r0 = (rg - 4) * 32; mode = 2; }

    for (int i = threadIdx.x; i < 32 * 256; i += 128) {
        int r = i >> 8, c = i & 255;
        sW[c * 36 + r] = W[(size_t)(r0 + r) * C_ + c];
    }
    __syncthreads();

    const int n = blockIdx.x * 128 + threadIdx.x;
    const float* fb = feat + (size_t)b * C_ * N_;

    unsigned long long acc2[16];
#pragma unroll
    for (int i = 0; i < 16; i++) acc2[i] = 0ULL;

#pragma unroll 4
    for (int c = 0; c < C_; c++) {
        float x = __ldg(fb + (size_t)c * N_ + n);
        unsigned long long x2 = pack2(x);
        const ulonglong2* wv = (const ulonglong2*)(sW + c * 36);
#pragma unroll
        for (int r = 0; r < 8; r++) {
            ulonglong2 wq = wv[r];
            acc2[2 * r]     = ffma2(x2, wq.x, acc2[2 * r]);
            acc2[2 * r + 1] = ffma2(x2, wq.y, acc2[2 * r + 1]);
        }
    }

    float v[32];
#pragma unroll
    for (int i = 0; i < 16; i++) {
        float2 t = unpack2(acc2[i]);
        v[2 * i] = t.x; v[2 * i + 1] = t.y;
    }

    const size_t nb = (size_t)b * N_ + n;
    if (mode == 2) {
        float* dst = g_Ht + nb * C_ + r0;
#pragma unroll
        for (int j = 0; j < 8; j++) {
            float4 o;
            o.x = __uint_as_float(tf32_of(v[4 * j + 0]));
            o.y = __uint_as_float(tf32_of(v[4 * j + 1]));
            o.z = __uint_as_float(tf32_of(v[4 * j + 2]));
            o.w = __uint_as_float(tf32_of(v[4 * j + 3]));
            *(float4*)(dst + 4 * j) = o;
        }
    } else {
        const float scale = (mode == 1) ? LOG2E : 1.0f;
        float* dh = (mode == 1 ? g_Gh : g_Fh) + nb * K_ + r0;
        float* dl = (mode == 1 ? g_Gl : g_Fl) + nb * K_ + r0;
#pragma unroll
        for (int j = 0; j < 8; j++) {
            float4 h4, l4;
            float hv, xv;
#pragma unroll
            for (int e = 0; e < 4; e++) {
                xv = v[4 * j + e] * scale;
                hv = __uint_as_float(tf32_of(xv));
                ((float*)&h4)[e] = hv;
                ((float*)&l4)[e] = __uint_as_float(tf32_of(xv - hv));
            }
            *(float4*)(dh + 4 * j) = h4;
            *(float4*)(dl + 4 * j) = l4;
        }
    }
}

// ---------------------------------------------------------------------------
// TF32 flash attention, cp.async double-buffered over 32-row m-tiles.
// Block = 128 q-rows, 8 warps, warp = 16 rows x 256 d.
// S = 3xTF32 (hi/lo G,F). PV = 1xTF32 (P tf32-rounded; softmax cancels).
// ---------------------------------------------------------------------------
#define PADK 68
#define PADH 260
#define SGH 0
#define SGL (128 * PADK)                 // 8704
#define SFB (2 * 128 * PADK)             // 17408: F bufs [buf][hl] 32x68 each
#define FPL (MT * PADK)                  // 2176 floats per F plane
#define SHB (SFB + 4 * FPL)              // 26112: H bufs [buf] 32x260
#define HPL (MT * PADH)                  // 8320 floats per H plane
#define SMEMF (SHB + 2 * HPL)            // 42752 floats
#define SMEMB (SMEMF * 4)                // 171008 bytes

__global__ __launch_bounds__(256, 1) void attn_kernel(
    const float* __restrict__ input,
    const float* __restrict__ gamma_p,
    float* __restrict__ out)
{
    extern __shared__ float sm[];
    uint32_t smu;
    asm("{ .reg .u64 t; cvta.to.shared.u64 t, %1; cvt.u32.u64 %0, t; }"
        : "=r"(smu) : "l"(sm));

    const int tid  = threadIdx.x;
    const int lane = tid & 31;
    const int w    = tid >> 5;       // warp 0..7, owns rows [16w,16w+16)
    const int gr   = lane >> 2;
    const int tg   = lane & 3;
    const int n0   = blockIdx.x * 128;
    const int b    = blockIdx.y;

    const float4* FH = (const float4*)(g_Fh + (size_t)b * N_ * K_);
    const float4* FL = (const float4*)(g_Fl + (size_t)b * N_ * K_);
    const float4* HT = (const float4*)(g_Ht + (size_t)b * N_ * C_);

    // stage G tile (128 x 64, hi+lo) once
    {
        const float4* GH = (const float4*)(g_Gh + ((size_t)b * N_ + n0) * K_);
        const float4* GL = (const float4*)(g_Gl + ((size_t)b * N_ + n0) * K_);
        for (int i = tid; i < 128 * 16; i += 256) {
            int r = i >> 4, k4 = i & 15;
            *(float4*)(sm + SGH + r * PADK + k4 * 4) = GH[i];
            *(float4*)(sm + SGL + r * PADK + k4 * 4) = GL[i];
        }
    }

    // prefetch m-tile 0 into buf 0
    {
        const int m0 = 0;
#pragma unroll
        for (int i = tid; i < 1024; i += 256) {
            int hl = i >> 9, j = i & 511, r = j >> 4, k4 = j & 15;
            uint32_t dst = smu + (SFB + hl * FPL + r * PADK + k4 * 4) * 4;
            cp16(dst, (hl ? FL : FH) + (size_t)(m0 + r) * 16 + k4);
        }
#pragma unroll
        for (int i = tid; i < 2048; i += 256) {
            int r = i >> 6, d4 = i & 63;
            uint32_t dst = smu + (SHB + r * PADH + d4 * 4) * 4;
            cp16(dst, HT + (size_t)(m0 + r) * 64 + d4);
        }
        cp_commit();
    }

    float oacc[32][4];
#pragma unroll
    for (int i = 0; i < 32; i++) {
        oacc[i][0] = 0.f; oacc[i][1] = 0.f; oacc[i][2] = 0.f; oacc[i][3] = 0.f;
    }
    const float NEG_INF = __int_as_float(0xff800000);
    float mrow0 = NEG_INF, mrow1 = NEG_INF, lsum0 = 0.f, lsum1 = 0.f;

    const float* gh = sm + SGH + (w * 16 + gr) * PADK;
    const float* gl = sm + SGL + (w * 16 + gr) * PADK;

#pragma unroll 1
    for (int t = 0; t < N_ / MT; t++) {
        cp_wait0();
        __syncthreads();   // tile t landed; buf[(t+1)&1] fully consumed

        const int cur = t & 1;
        if (t + 1 < N_ / MT) {     // prefetch t+1 into the other buffer
            const int m0n = (t + 1) * MT;
            const int nb = cur ^ 1;
#pragma unroll
            for (int i = tid; i < 1024; i += 256) {
                int hl = i >> 9, j = i & 511, r = j >> 4, k4 = j & 15;
                uint32_t dst = smu + (SFB + (nb * 2 + hl) * FPL + r * PADK + k4 * 4) * 4;
                cp16(dst, (hl ? FL : FH) + (size_t)(m0n + r) * 16 + k4);
            }
#pragma unroll
            for (int i = tid; i < 2048; i += 256) {
                int r = i >> 6, d4 = i & 63;
                uint32_t dst = smu + (SHB + nb * HPL + r * PADH + d4 * 4) * 4;
                cp16(dst, HT + (size_t)(m0n + r) * 64 + d4);
            }
            cp_commit();
        }

        const float* sFh = sm + SFB + (cur * 2) * FPL;
        const float* sHc = sm + SHB + cur * HPL;

        // ---- S tile: sc[ms] = 16n x 8m C-frags, 3xTF32 ----
        float sc[4][4];
#pragma unroll
        for (int ms = 0; ms < 4; ms++) {
            sc[ms][0] = 0.f; sc[ms][1] = 0.f; sc[ms][2] = 0.f; sc[ms][3] = 0.f;
        }
#pragma unroll
        for (int kc = 0; kc < 8; kc++) {
            const int ko = kc * 8 + tg;
            uint32_t ah0 = __float_as_uint(gh[ko]);
            uint32_t ah1 = __float_as_uint(gh[8 * PADK + ko]);
            uint32_t ah2 = __float_as_uint(gh[ko + 4]);
            uint32_t ah3 = __float_as_uint(gh[8 * PADK + ko + 4]);
            uint32_t al0 = __float_as_uint(gl[ko]);
            uint32_t al1 = __float_as_uint(gl[8 * PADK + ko]);
            uint32_t al2 = __float_as_uint(gl[ko + 4]);
            uint32_t al3 = __float_as_uint(gl[8 * PADK + ko + 4]);
#pragma unroll
            for (int ms = 0; ms < 4; ms++) {
                const float* fh = sFh + (ms * 8 + gr) * PADK + ko;
                uint32_t bh0 = __float_as_uint(fh[0]);
                uint32_t bh1 = __float_as_uint(fh[4]);
                uint32_t bl0 = __float_as_uint(fh[FPL]);
                uint32_t bl1 = __float_as_uint(fh[FPL + 4]);
                mma_tf32(sc[ms], ah0, ah1, ah2, ah3, bh0, bh1);
                mma_tf32(sc[ms], ah0, ah1, ah2, ah3, bl0, bl1);
                mma_tf32(sc[ms], al0, al1, al2, al3, bh0, bh1);
            }
        }

        // ---- online softmax (log2 domain) with lazy O-rescale ----
        float t0 = NEG_INF, t1 = NEG_INF;
#pragma unroll
        for (int ms = 0; ms < 4; ms++) {
            t0 = fmaxf(t0, fmaxf(sc[ms][0], sc[ms][1]));
            t1 = fmaxf(t1, fmaxf(sc[ms][2], sc[ms][3]));
        }
        t0 = fmaxf(t0, __shfl_xor_sync(0xffffffffu, t0, 1));
        t0 = fmaxf(t0, __shfl_xor_sync(0xffffffffu, t0, 2));
        t1 = fmaxf(t1, __shfl_xor_sync(0xffffffffu, t1, 1));
        t1 = fmaxf(t1, __shfl_xor_sync(0xffffffffu, t1, 2));

        const float mn0 = fmaxf(mrow0, t0);
        const float mn1 = fmaxf(mrow1, t1);
        const bool up = (mn0 != mrow0) || (mn1 != mrow1);
        if (__any_sync(0xffffffffu, up)) {
            const float cr0 = ex2(mrow0 - mn0);   // 0 on first tile (-inf)
            const float cr1 = ex2(mrow1 - mn1);
            lsum0 *= cr0; lsum1 *= cr1;
#pragma unroll
            for (int dt = 0; dt < 32; dt++) {
                oacc[dt][0] *= cr0; oacc[dt][1] *= cr0;
                oacc[dt][2] *= cr1; oacc[dt][3] *= cr1;
            }
            mrow0 = mn0; mrow1 = mn1;
        }
#pragma unroll
        for (int ms = 0; ms < 4; ms++) {
            sc[ms][0] = ex2(sc[ms][0] - mrow0);
            sc[ms][1] = ex2(sc[ms][1] - mrow0);
            sc[ms][2] = ex2(sc[ms][2] - mrow1);
            sc[ms][3] = ex2(sc[ms][3] - mrow1);
            lsum0 += sc[ms][0] + sc[ms][1];
            lsum1 += sc[ms][2] + sc[ms][3];
        }

        // ---- PV: O += P * H, 1xTF32. C->A frag: a={c0,c2,c1,c3};
        //      A col k holds m=2k (k<4) / 2(k-4)+1, compensated in B rows. ----
#pragma unroll
        for (int mc = 0; mc < 4; mc++) {
            uint32_t p0 = tf32_of(sc[mc][0]);
            uint32_t p1 = tf32_of(sc[mc][2]);
            uint32_t p2 = tf32_of(sc[mc][1]);
            uint32_t p3 = tf32_of(sc[mc][3]);
            const float* hb = sHc + (mc * 8 + 2 * tg) * PADH + gr;
#pragma unroll
            for (int dt = 0; dt < 32; dt++) {
                uint32_t b0 = __float_as_uint(hb[dt * 8]);
                uint32_t b1 = __float_as_uint(hb[PADH + dt * 8]);
                mma_tf32(oacc[dt], p0, p1, p2, p3, b0, b1);
            }
        }
    }

    // ---- epilogue: l reduce, out = gamma*(O/l) + input, flat [B,N,C] ----
    lsum0 += __shfl_xor_sync(0xffffffffu, lsum0, 1);
    lsum0 += __shfl_xor_sync(0xffffffffu, lsum0, 2);
    lsum1 += __shfl_xor_sync(0xffffffffu, lsum1, 1);
    lsum1 += __shfl_xor_sync(0xffffffffu, lsum1, 2);
    const float inv0 = 1.0f / lsum0;
    const float inv1 = 1.0f / lsum1;
    const float gm = __ldg(gamma_p);

    const int r0 = n0 + w * 16 + gr;
    const int r1 = r0 + 8;
    const size_t base0 = ((size_t)b * N_ + r0) * C_ + tg * 2;
    const size_t base1 = ((size_t)b * N_ + r1) * C_ + tg * 2;
#pragma unroll
    for (int dt = 0; dt < 32; dt++) {
        float2 iv0 = *(const float2*)(input + base0 + dt * 8);
        float2 iv1 = *(const float2*)(input + base1 + dt * 8);
        float2 ov0, ov1;
        ov0.x = fmaf(gm, oacc[dt][0] * inv0, iv0.x);
        ov0.y = fmaf(gm, oacc[dt][1] * inv0, iv0.y);
        ov1.x = fmaf(gm, oacc[dt][2] * inv1, iv1.x);
        ov1.y = fmaf(gm, oacc[dt][3] * inv1, iv1.y);
        *(float2*)(out + base0 + dt * 8) = ov0;
        *(float2*)(out + base1 + dt * 8) = ov1;
    }
}

// ---------------------------------------------------------------------------
extern "C" void kernel_launch(void* const* d_in, const int* in_sizes, int n_in,
                              void* d_out, int out_size) {
    (void)in_sizes; (void)n_in; (void)out_size;
    const float* input = (const float*)d_in[0];
    const float* feat  = (const float*)d_in[1];   // nms_feat
    const float* WF    = (const float*)d_in[2];
    const float* WG    = (const float*)d_in[3];
    const float* WH    = (const float*)d_in[4];
    const float* gamma = (const float*)d_in[5];
    float* out = (float*)d_out;

    cudaFuncSetAttribute(attn_kernel,
                         cudaFuncAttributeMaxDynamicSharedMemorySize, SMEMB);

    proj_kernel<<<dim3(N_ / 128, 12, B_), 128>>>(feat, WF, WG, WH);
    attn_kernel<<<dim3(N_ / 128, B_), 256, SMEMB>>>(input, gamma, out);
}

// round 5
// speedup vs baseline: 4.8762x; 1.2435x over previous
#include <cuda_runtime.h>
#include <cstdint>

#define B_ 8
#define C_ 256
#define N_ 4096
#define K_ 64
#define MT 32
#define LOG2E 1.4426950408889634f

// Scratch (bf16 hi/lo packed). F/G rows: 64 u32 = [hi-pair0, lo-pair0, hi-pair1, ...]
// pair p = (k=2p, k=2p+1). H: bf16 hi only, TRANSPOSED [b][d][n].
__device__ uint32_t g_F[(size_t)B_ * N_ * 64];
__device__ uint32_t g_G[(size_t)B_ * N_ * 64];     // pre-scaled by log2(e)
__device__ uint16_t g_H[(size_t)B_ * C_ * N_];

// ---------------- helpers ----------------
__device__ __forceinline__ uint32_t bf16x2(float lo, float hi) {
    uint32_t r;  // d<15:0>=cvt(b-operand)=lo, d<31:16>=cvt(a-operand)=hi
    asm("cvt.rn.bf16x2.f32 %0, %1, %2;" : "=r"(r) : "f"(hi), "f"(lo));
    return r;
}
__device__ __forceinline__ float bflo(uint32_t p) { return __uint_as_float(p << 16); }
__device__ __forceinline__ float bfhi(uint32_t p) { return __uint_as_float(p & 0xffff0000u); }
__device__ __forceinline__ float ex2(float x) {
    float r; asm("ex2.approx.f32 %0, %1;" : "=f"(r) : "f"(x)); return r;
}
__device__ __forceinline__ void mma_bf16(float* c,
    uint32_t a0, uint32_t a1, uint32_t a2, uint32_t a3,
    uint32_t b0, uint32_t b1) {
    asm volatile("mma.sync.aligned.m16n8k16.row.col.f32.bf16.bf16.f32 "
        "{%0,%1,%2,%3},{%4,%5,%6,%7},{%8,%9},{%0,%1,%2,%3};"
        : "+f"(c[0]), "+f"(c[1]), "+f"(c[2]), "+f"(c[3])
        : "r"(a0), "r"(a1), "r"(a2), "r"(a3), "r"(b0), "r"(b1));
}
__device__ __forceinline__ void cp16(uint32_t dst, const void* src) {
    asm volatile("cp.async.cg.shared.global [%0], [%1], 16;" :: "r"(dst), "l"(src));
}
__device__ __forceinline__ void cp_commit() { asm volatile("cp.async.commit_group;"); }
__device__ __forceinline__ void cp_wait0()  { asm volatile("cp.async.wait_group 0;"); }
__device__ __forceinline__ unsigned long long ffma2(unsigned long long a,
                                                    unsigned long long b,
                                                    unsigned long long c) {
    unsigned long long d;
    asm("fma.rn.f32x2 %0, %1, %2, %3;" : "=l"(d) : "l"(a), "l"(b), "l"(c));
    return d;
}
__device__ __forceinline__ unsigned long long pack2(float x) {
    unsigned long long r;
    unsigned int xi = __float_as_uint(x);
    asm("mov.b64 %0, {%1, %1};" : "=l"(r) : "r"(xi));
    return r;
}
__device__ __forceinline__ float2 unpack2(unsigned long long v) {
    unsigned int lo, hi;
    asm("mov.b64 {%0, %1}, %2;" : "=r"(lo), "=r"(hi) : "l"(v));
    return make_float2(__uint_as_float(lo), __uint_as_float(hi));
}

// ---------------------------------------------------------------------------
// Projection: rg 0-1 -> F (bf16 hi/lo), 2-3 -> G (scaled, hi/lo),
//             4-11 -> H (bf16, transposed [d][n]). 32 output rows per block.
// ---------------------------------------------------------------------------
__global__ __launch_bounds__(128) void proj_kernel(
    const float* __restrict__ feat,
    const float* __restrict__ WF,
    const float* __restrict__ WG,
    const float* __restrict__ WH)
{
    __shared__ float sW[256 * 36];
    const int rg = blockIdx.y;
    const int b  = blockIdx.z;

    const float* W;
    int r0, mode;                      // 0=F, 1=G, 2=H
    if (rg < 2)      { W = WF; r0 = rg * 32;       mode = 0; }
    else if (rg < 4) { W = WG; r0 = (rg - 2) * 32; mode = 1; }
    else             { W = WH; r0 = (rg - 4) * 32; mode = 2; }

    for (int i = threadIdx.x; i < 32 * 256; i += 128) {
        int r = i >> 8, c = i & 255;
        sW[c * 36 + r] = W[(size_t)(r0 + r) * C_ + c];
    }
    __syncthreads();

    const int n = blockIdx.x * 128 + threadIdx.x;
    const float* fb = feat + (size_t)b * C_ * N_;

    unsigned long long acc2[16];
#pragma unroll
    for (int i = 0; i < 16; i++) acc2[i] = 0ULL;

#pragma unroll 4
    for (int c = 0; c < C_; c++) {
        float x = __ldg(fb + (size_t)c * N_ + n);
        unsigned long long x2 = pack2(x);
        const ulonglong2* wv = (const ulonglong2*)(sW + c * 36);
#pragma unroll
        for (int r = 0; r < 8; r++) {
            ulonglong2 wq = wv[r];
            acc2[2 * r]     = ffma2(x2, wq.x, acc2[2 * r]);
            acc2[2 * r + 1] = ffma2(x2, wq.y, acc2[2 * r + 1]);
        }
    }

    float v[32];
#pragma unroll
    for (int i = 0; i < 16; i++) {
        float2 t = unpack2(acc2[i]);
        v[2 * i] = t.x; v[2 * i + 1] = t.y;
    }

    const size_t nb = (size_t)b * N_ + n;
    if (mode == 2) {
        // H: bf16, transposed: g_H[b][d = r0+j][n]
        uint16_t* dst = g_H + ((size_t)b * C_ + r0) * N_ + n;
#pragma unroll
        for (int j = 0; j < 32; j++) {
            uint32_t p = bf16x2(v[j], 0.0f);
            dst[(size_t)j * N_] = (uint16_t)(p & 0xffffu);
        }
    } else {
        const float scale = (mode == 1) ? LOG2E : 1.0f;
        uint32_t* dst = (mode == 1 ? g_G : g_F) + nb * 64 + r0;  // r0/2 pairs * 2
#pragma unroll
        for (int j = 0; j < 16; j++) {
            float x0 = v[2 * j] * scale, x1 = v[2 * j + 1] * scale;
            uint32_t hi2 = bf16x2(x0, x1);
            uint32_t lo2 = bf16x2(x0 - bflo(hi2), x1 - bfhi(hi2));
            uint2 o; o.x = hi2; o.y = lo2;
            *(uint2*)(dst + 2 * j) = o;
        }
    }
}

// ---------------------------------------------------------------------------
// bf16 hi/lo flash attention. Block = 128 q-rows, 8 warps, warp = 16 rows x 256 d.
// m-tiles of 32, cp.async double-buffered.
// S = 3-pass bf16 (Gh.Fh + Gh.Fl + Gl.Fh), m16n8k16.
// PV = 2-pass (Ph.H + Pl.H), H bf16 single, stored transposed for LDS.32 B-frags.
// ---------------------------------------------------------------------------
#define GROW 72                          // u32 per G/F smem row (64 + pad)
#define HROW 20                          // u32 per H smem row (16 + pad)
#define SG  0                            // 128 * 72 = 9216 u32
#define SF  (128 * GROW)                 // 2 bufs * 32 * 72 = 4608 u32
#define FPL (MT * GROW)                  // 2304
#define SH  (SF + 2 * FPL)               // 2 bufs * 256 * 20 = 10240 u32
#define HPL (C_ * HROW)                  // 5120
#define SMEMU (SH + 2 * HPL)             // 24064 u32
#define SMEMB (SMEMU * 4)                // 96256 B

__global__ __launch_bounds__(256, 1) void attn_kernel(
    const float* __restrict__ input,
    const float* __restrict__ gamma_p,
    float* __restrict__ out)
{
    extern __shared__ uint32_t sm[];
    uint32_t smu;
    asm("{ .reg .u64 t; cvta.to.shared.u64 t, %1; cvt.u32.u64 %0, t; }"
        : "=r"(smu) : "l"(sm));

    const int tid  = threadIdx.x;
    const int lane = tid & 31;
    const int w    = tid >> 5;
    const int gr   = lane >> 2;
    const int tg   = lane & 3;
    const int n0   = blockIdx.x * 128;
    const int b    = blockIdx.y;

    const uint32_t* FG = g_F + (size_t)b * N_ * 64;
    const uint32_t* HG = (const uint32_t*)(g_H + (size_t)b * C_ * N_); // [d][n] bf16

    // stage G tile (128 rows x 64 u32) once via cp.async
    {
        const uint32_t* GG = g_G + ((size_t)b * N_ + n0) * 64;
        for (int i = tid; i < 128 * 16; i += 256) {
            int r = i >> 4, ch = i & 15;
            cp16(smu + (SG + r * GROW + ch * 4) * 4, GG + r * 64 + ch * 4);
        }
    }
    // prefetch m-tile 0 into buf 0
    {
        for (int i = tid; i < 512; i += 256) {
            int r = i >> 4, ch = i & 15;
            cp16(smu + (SF + r * GROW + ch * 4) * 4, FG + (size_t)r * 64 + ch * 4);
        }
        for (int i = tid; i < 1024; i += 256) {
            int r = i >> 2, ch = i & 3;   // r = d 0..255
            cp16(smu + (SH + r * HROW + ch * 4) * 4, HG + (size_t)r * 2048 + ch * 4);
        }
        cp_commit();
    }

    float oacc[32][4];
#pragma unroll
    for (int i = 0; i < 32; i++) {
        oacc[i][0] = 0.f; oacc[i][1] = 0.f; oacc[i][2] = 0.f; oacc[i][3] = 0.f;
    }
    const float NEG_INF = __int_as_float(0xff800000);
    float mrow0 = NEG_INF, mrow1 = NEG_INF, lsum0 = 0.f, lsum1 = 0.f;

    const uint32_t* g0 = sm + SG + (w * 16 + gr) * GROW;      // row gr
    const uint32_t* g1 = g0 + 8 * GROW;                       // row gr+8

#pragma unroll 1
    for (int t = 0; t < N_ / MT; t++) {
        cp_wait0();
        __syncthreads();

        const int cur = t & 1;
        if (t + 1 < N_ / MT) {
            const int m0n = (t + 1) * MT;
            const int nb = cur ^ 1;
            for (int i = tid; i < 512; i += 256) {
                int r = i >> 4, ch = i & 15;
                cp16(smu + (SF + nb * FPL + r * GROW + ch * 4) * 4,
                     FG + (size_t)(m0n + r) * 64 + ch * 4);
            }
            for (int i = tid; i < 1024; i += 256) {
                int r = i >> 2, ch = i & 3;
                cp16(smu + (SH + nb * HPL + r * HROW + ch * 4) * 4,
                     HG + (size_t)r * 2048 + m0n / 2 + ch * 4);
            }
            cp_commit();
        }

        const uint32_t* sFc = sm + SF + cur * FPL;
        const uint32_t* sHc = sm + SH + cur * HPL;

        // ---- S tile: sc[ms] = 16n x 8m C-frags, 3-pass bf16 k16 ----
        float sc[4][4];
#pragma unroll
        for (int ms = 0; ms < 4; ms++) {
            sc[ms][0] = 0.f; sc[ms][1] = 0.f; sc[ms][2] = 0.f; sc[ms][3] = 0.f;
        }
#pragma unroll
        for (int kc = 0; kc < 4; kc++) {
            const int o0 = kc * 16 + 2 * tg;
            uint2 A0 = *(const uint2*)(g0 + o0);       // (a0h, a0l)
            uint2 A2 = *(const uint2*)(g0 + o0 + 8);   // (a2h, a2l)
            uint2 A1 = *(const uint2*)(g1 + o0);
            uint2 A3 = *(const uint2*)(g1 + o0 + 8);
#pragma unroll
            for (int ms = 0; ms < 4; ms++) {
                const uint32_t* f = sFc + (ms * 8 + gr) * GROW;
                uint2 B0 = *(const uint2*)(f + o0);
                uint2 B1 = *(const uint2*)(f + o0 + 8);
                mma_bf16(sc[ms], A0.x, A1.x, A2.x, A3.x, B0.x, B1.x);
                mma_bf16(sc[ms], A0.x, A1.x, A2.x, A3.x, B0.y, B1.y);
                mma_bf16(sc[ms], A0.y, A1.y, A2.y, A3.y, B0.x, B1.x);
            }
        }

        // ---- online softmax (log2 domain), lazy O-rescale ----
        float t0 = NEG_INF, t1 = NEG_INF;
#pragma unroll
        for (int ms = 0; ms < 4; ms++) {
            t0 = fmaxf(t0, fmaxf(sc[ms][0], sc[ms][1]));
            t1 = fmaxf(t1, fmaxf(sc[ms][2], sc[ms][3]));
        }
        t0 = fmaxf(t0, __shfl_xor_sync(0xffffffffu, t0, 1));
        t0 = fmaxf(t0, __shfl_xor_sync(0xffffffffu, t0, 2));
        t1 = fmaxf(t1, __shfl_xor_sync(0xffffffffu, t1, 1));
        t1 = fmaxf(t1, __shfl_xor_sync(0xffffffffu, t1, 2));

        const float mn0 = fmaxf(mrow0, t0);
        const float mn1 = fmaxf(mrow1, t1);
        const bool up = (mn0 != mrow0) || (mn1 != mrow1);
        if (__any_sync(0xffffffffu, up)) {
            const float cr0 = ex2(mrow0 - mn0);
            const float cr1 = ex2(mrow1 - mn1);
            lsum0 *= cr0; lsum1 *= cr1;
#pragma unroll
            for (int dt = 0; dt < 32; dt++) {
                oacc[dt][0] *= cr0; oacc[dt][1] *= cr0;
                oacc[dt][2] *= cr1; oacc[dt][3] *= cr1;
            }
            mrow0 = mn0; mrow1 = mn1;
        }
#pragma unroll
        for (int ms = 0; ms < 4; ms++) {
            sc[ms][0] = ex2(sc[ms][0] - mrow0);
            sc[ms][1] = ex2(sc[ms][1] - mrow0);
            sc[ms][2] = ex2(sc[ms][2] - mrow1);
            sc[ms][3] = ex2(sc[ms][3] - mrow1);
            lsum0 += sc[ms][0] + sc[ms][1];
            lsum1 += sc[ms][2] + sc[ms][3];
        }

        // ---- PV: O += P * H, 2-pass bf16 (P hi/lo exact, H bf16) ----
#pragma unroll
        for (int j = 0; j < 2; j++) {
            const float* cA = sc[2 * j];       // k = 2tg,2tg+1 (cols of frag 2j)
            const float* cB = sc[2 * j + 1];   // k = 2tg+8,2tg+9
            uint32_t ph0 = bf16x2(cA[0], cA[1]);
            uint32_t ph1 = bf16x2(cA[2], cA[3]);
            uint32_t ph2 = bf16x2(cB[0], cB[1]);
            uint32_t ph3 = bf16x2(cB[2], cB[3]);
            uint32_t pl0 = bf16x2(cA[0] - bflo(ph0), cA[1] - bfhi(ph0));
            uint32_t pl1 = bf16x2(cA[2] - bflo(ph1), cA[3] - bfhi(ph1));
            uint32_t pl2 = bf16x2(cB[0] - bflo(ph2), cB[1] - bfhi(ph2));
            uint32_t pl3 = bf16x2(cB[2] - bflo(ph3), cB[3] - bfhi(ph3));
            const uint32_t* hb = sHc + gr * HROW + j * 8;
#pragma unroll
            for (int dt = 0; dt < 32; dt++) {
                const uint32_t* hr = hb + dt * 8 * HROW;
                uint32_t b0 = hr[tg];
                uint32_t b1 = hr[tg + 4];
                mma_bf16(oacc[dt], ph0, ph1, ph2, ph3, b0, b1);
                mma_bf16(oacc[dt], pl0, pl1, pl2, pl3, b0, b1);
            }
        }
    }

    // ---- epilogue: l reduce, out = gamma*(O/l) + input, flat [B,N,C] ----
    lsum0 += __shfl_xor_sync(0xffffffffu, lsum0, 1);
    lsum0 += __shfl_xor_sync(0xffffffffu, lsum0, 2);
    lsum1 += __shfl_xor_sync(0xffffffffu, lsum1, 1);
    lsum1 += __shfl_xor_sync(0xffffffffu, lsum1, 2);
    const float inv0 = 1.0f / lsum0;
    const float inv1 = 1.0f / lsum1;
    const float gm = __ldg(gamma_p);

    const int r0 = n0 + w * 16 + gr;
    const int r1 = r0 + 8;
    const size_t base0 = ((size_t)b * N_ + r0) * C_ + tg * 2;
    const size_t base1 = ((size_t)b * N_ + r1) * C_ + tg * 2;
#pragma unroll
    for (int dt = 0; dt < 32; dt++) {
        float2 iv0 = *(const float2*)(input + base0 + dt * 8);
        float2 iv1 = *(const float2*)(input + base1 + dt * 8);
        float2 ov0, ov1;
        ov0.x = fmaf(gm, oacc[dt][0] * inv0, iv0.x);
        ov0.y = fmaf(gm, oacc[dt][1] * inv0, iv0.y);
        ov1.x = fmaf(gm, oacc[dt][2] * inv1, iv1.x);
        ov1.y = fmaf(gm, oacc[dt][3] * inv1, iv1.y);
        *(float2*)(out + base0 + dt * 8) = ov0;
        *(float2*)(out + base1 + dt * 8) = ov1;
    }
}

// ---------------------------------------------------------------------------
extern "C" void kernel_launch(void* const* d_in, const int* in_sizes, int n_in,
                              void* d_out, int out_size) {
    (void)in_sizes; (void)n_in; (void)out_size;
    const float* input = (const float*)d_in[0];
    const float* feat  = (const float*)d_in[1];   // nms_feat
    const float* WF    = (const float*)d_in[2];
    const float* WG    = (const float*)d_in[3];
    const float* WH    = (const float*)d_in[4];
    const float* gamma = (const float*)d_in[5];
    float* out = (float*)d_out;

    cudaFuncSetAttribute(attn_kernel,
                         cudaFuncAttributeMaxDynamicSharedMemorySize, SMEMB);

    proj_kernel<<<dim3(N_ / 128, 12, B_), 128>>>(feat, WF, WG, WH);
    attn_kernel<<<dim3(N_ / 128, B_), 256, SMEMB>>>(input, gamma, out);
}

// round 6
// speedup vs baseline: 5.8825x; 1.2064x over previous
#include <cuda_runtime.h>
#include <cuda_fp16.h>
#include <cstdint>

#define B_ 8
#define C_ 256
#define N_ 4096
#define K_ 64
#define MT 32
#define LOG2E 1.4426950408889634f

// Scratch (fp16 hi/lo packed). F/G rows: 64 u32 = [hi-pair0, lo-pair0, hi-pair1, ...]
// pair p = (k=2p, k=2p+1). H: fp16 single, TRANSPOSED [b][d][n].
__device__ uint32_t g_F[(size_t)B_ * N_ * 64];
__device__ uint32_t g_G[(size_t)B_ * N_ * 64];     // pre-scaled by log2(e)
__device__ uint16_t g_H[(size_t)B_ * C_ * N_];

// ---------------- helpers ----------------
__device__ __forceinline__ uint32_t f16x2(float lo, float hi) {
    uint32_t r;  // d<15:0>=cvt(b)=lo, d<31:16>=cvt(a)=hi
    asm("cvt.rn.f16x2.f32 %0, %1, %2;" : "=r"(r) : "f"(hi), "f"(lo));
    return r;
}
__device__ __forceinline__ float f16lo(uint32_t p) {
    return __half2float(__ushort_as_half((unsigned short)(p & 0xffffu)));
}
__device__ __forceinline__ float f16hi(uint32_t p) {
    return __half2float(__ushort_as_half((unsigned short)(p >> 16)));
}
__device__ __forceinline__ float ex2(float x) {
    float r; asm("ex2.approx.f32 %0, %1;" : "=f"(r) : "f"(x)); return r;
}
__device__ __forceinline__ void mma_f16(float* c,
    uint32_t a0, uint32_t a1, uint32_t a2, uint32_t a3,
    uint32_t b0, uint32_t b1) {
    asm volatile("mma.sync.aligned.m16n8k16.row.col.f32.f16.f16.f32 "
        "{%0,%1,%2,%3},{%4,%5,%6,%7},{%8,%9},{%0,%1,%2,%3};"
        : "+f"(c[0]), "+f"(c[1]), "+f"(c[2]), "+f"(c[3])
        : "r"(a0), "r"(a1), "r"(a2), "r"(a3), "r"(b0), "r"(b1));
}
__device__ __forceinline__ void cp16(uint32_t dst, const void* src) {
    asm volatile("cp.async.cg.shared.global [%0], [%1], 16;" :: "r"(dst), "l"(src));
}
__device__ __forceinline__ void cp_commit() { asm volatile("cp.async.commit_group;"); }
__device__ __forceinline__ void cp_wait0()  { asm volatile("cp.async.wait_group 0;"); }
__device__ __forceinline__ unsigned long long ffma2(unsigned long long a,
                                                    unsigned long long b,
                                                    unsigned long long c) {
    unsigned long long d;
    asm("fma.rn.f32x2 %0, %1, %2, %3;" : "=l"(d) : "l"(a), "l"(b), "l"(c));
    return d;
}
__device__ __forceinline__ unsigned long long pack2(float x) {
    unsigned long long r;
    unsigned int xi = __float_as_uint(x);
    asm("mov.b64 %0, {%1, %1};" : "=l"(r) : "r"(xi));
    return r;
}
__device__ __forceinline__ float2 unpack2(unsigned long long v) {
    unsigned int lo, hi;
    asm("mov.b64 {%0, %1}, %2;" : "=r"(lo), "=r"(hi) : "l"(v));
    return make_float2(__uint_as_float(lo), __uint_as_float(hi));
}

// ---------------------------------------------------------------------------
// Projection: rg 0-1 -> F (fp16 hi/lo), 2-3 -> G (scaled, hi/lo),
//             4-11 -> H (fp16, transposed [d][n]). 32 output rows per block.
// ---------------------------------------------------------------------------
__global__ __launch_bounds__(128) void proj_kernel(
    const float* __restrict__ feat,
    const float* __restrict__ WF,
    const float* __restrict__ WG,
    const float* __restrict__ WH)
{
    __shared__ float sW[256 * 36];
    const int rg = blockIdx.y;
    const int b  = blockIdx.z;

    const float* W;
    int r0, mode;                      // 0=F, 1=G, 2=H
    if (rg < 2)      { W = WF; r0 = rg * 32;       mode = 0; }
    else if (rg < 4) { W = WG; r0 = (rg - 2) * 32; mode = 1; }
    else             { W = WH; r0 = (rg - 4) * 32; mode = 2; }

    for (int i = threadIdx.x; i < 32 * 256; i += 128) {
        int r = i >> 8, c = i & 255;
        sW[c * 36 + r] = W[(size_t)(r0 + r) * C_ + c];
    }
    __syncthreads();

    const int n = blockIdx.x * 128 + threadIdx.x;
    const float* fb = feat + (size_t)b * C_ * N_;

    unsigned long long acc2[16];
#pragma unroll
    for (int i = 0; i < 16; i++) acc2[i] = 0ULL;

#pragma unroll 4
    for (int c = 0; c < C_; c++) {
        float x = __ldg(fb + (size_t)c * N_ + n);
        unsigned long long x2 = pack2(x);
        const ulonglong2* wv = (const ulonglong2*)(sW + c * 36);
#pragma unroll
        for (int r = 0; r < 8; r++) {
            ulonglong2 wq = wv[r];
            acc2[2 * r]     = ffma2(x2, wq.x, acc2[2 * r]);
            acc2[2 * r + 1] = ffma2(x2, wq.y, acc2[2 * r + 1]);
        }
    }

    float v[32];
#pragma unroll
    for (int i = 0; i < 16; i++) {
        float2 t = unpack2(acc2[i]);
        v[2 * i] = t.x; v[2 * i + 1] = t.y;
    }

    const size_t nb = (size_t)b * N_ + n;
    if (mode == 2) {
        // H: fp16, transposed: g_H[b][d = r0+j][n]
        uint16_t* dst = g_H + ((size_t)b * C_ + r0) * N_ + n;
#pragma unroll
        for (int j = 0; j < 32; j++) {
            dst[(size_t)j * N_] = __half_as_ushort(__float2half_rn(v[j]));
        }
    } else {
        const float scale = (mode == 1) ? LOG2E : 1.0f;
        uint32_t* dst = (mode == 1 ? g_G : g_F) + nb * 64 + r0;
#pragma unroll
        for (int j = 0; j < 16; j++) {
            float x0 = v[2 * j] * scale, x1 = v[2 * j + 1] * scale;
            uint32_t hi2 = f16x2(x0, x1);
            uint32_t lo2 = f16x2(x0 - f16lo(hi2), x1 - f16hi(hi2));
            uint2 o; o.x = hi2; o.y = lo2;
            *(uint2*)(dst + 2 * j) = o;
        }
    }
}

// ---------------------------------------------------------------------------
// fp16 hi/lo flash attention. Block = 128 q-rows, 8 warps, warp = 16 rows x 256 d.
// m-tiles of 32, cp.async double-buffered.
// S = 3-pass fp16 (Gh.Fh + Gh.Fl + Gl.Fh), m16n8k16 -> ~21-bit logits.
// PV = 1-pass (P fp16, H fp16); rounding ~2^-11 diluted by softmax + residual.
// ---------------------------------------------------------------------------
#define GROW 72                          // u32 per G/F smem row (64 + pad)
#define HROW 20                          // u32 per H smem row (16 + pad)
#define SG  0                            // 128 * 72 = 9216 u32
#define SF  (128 * GROW)
#define FPL (MT * GROW)                  // 2304
#define SH  (SF + 2 * FPL)
#define HPL (C_ * HROW)                  // 5120
#define SMEMU (SH + 2 * HPL)             // 24064 u32
#define SMEMB (SMEMU * 4)                // 96256 B

__global__ __launch_bounds__(256, 1) void attn_kernel(
    const float* __restrict__ input,
    const float* __restrict__ gamma_p,
    float* __restrict__ out)
{
    extern __shared__ uint32_t sm[];
    uint32_t smu;
    asm("{ .reg .u64 t; cvta.to.shared.u64 t, %1; cvt.u32.u64 %0, t; }"
        : "=r"(smu) : "l"(sm));

    const int tid  = threadIdx.x;
    const int lane = tid & 31;
    const int w    = tid >> 5;
    const int gr   = lane >> 2;
    const int tg   = lane & 3;
    const int n0   = blockIdx.x * 128;
    const int b    = blockIdx.y;

    const uint32_t* FG = g_F + (size_t)b * N_ * 64;
    const uint32_t* HG = (const uint32_t*)(g_H + (size_t)b * C_ * N_); // [d][n] fp16

    // stage G tile (128 rows x 64 u32) once via cp.async
    {
        const uint32_t* GG = g_G + ((size_t)b * N_ + n0) * 64;
        for (int i = tid; i < 128 * 16; i += 256) {
            int r = i >> 4, ch = i & 15;
            cp16(smu + (SG + r * GROW + ch * 4) * 4, GG + r * 64 + ch * 4);
        }
    }
    // prefetch m-tile 0 into buf 0
    {
        for (int i = tid; i < 512; i += 256) {
            int r = i >> 4, ch = i & 15;
            cp16(smu + (SF + r * GROW + ch * 4) * 4, FG + (size_t)r * 64 + ch * 4);
        }
        for (int i = tid; i < 1024; i += 256) {
            int r = i >> 2, ch = i & 3;   // r = d 0..255
            cp16(smu + (SH + r * HROW + ch * 4) * 4, HG + (size_t)r * 2048 + ch * 4);
        }
        cp_commit();
    }

    float oacc[32][4];
#pragma unroll
    for (int i = 0; i < 32; i++) {
        oacc[i][0] = 0.f; oacc[i][1] = 0.f; oacc[i][2] = 0.f; oacc[i][3] = 0.f;
    }
    const float NEG_INF = __int_as_float(0xff800000);
    float mrow0 = NEG_INF, mrow1 = NEG_INF, lsum0 = 0.f, lsum1 = 0.f;

    const uint32_t* g0 = sm + SG + (w * 16 + gr) * GROW;
    const uint32_t* g1 = g0 + 8 * GROW;

#pragma unroll 1
    for (int t = 0; t < N_ / MT; t++) {
        cp_wait0();
        __syncthreads();

        const int cur = t & 1;
        if (t + 1 < N_ / MT) {
            const int m0n = (t + 1) * MT;
            const int nb = cur ^ 1;
            for (int i = tid; i < 512; i += 256) {
                int r = i >> 4, ch = i & 15;
                cp16(smu + (SF + nb * FPL + r * GROW + ch * 4) * 4,
                     FG + (size_t)(m0n + r) * 64 + ch * 4);
            }
            for (int i = tid; i < 1024; i += 256) {
                int r = i >> 2, ch = i & 3;
                cp16(smu + (SH + nb * HPL + r * HROW + ch * 4) * 4,
                     HG + (size_t)r * 2048 + m0n / 2 + ch * 4);
            }
            cp_commit();
        }

        const uint32_t* sFc = sm + SF + cur * FPL;
        const uint32_t* sHc = sm + SH + cur * HPL;

        // ---- S tile: sc[ms] = 16n x 8m C-frags, 3-pass fp16 k16 ----
        float sc[4][4];
#pragma unroll
        for (int ms = 0; ms < 4; ms++) {
            sc[ms][0] = 0.f; sc[ms][1] = 0.f; sc[ms][2] = 0.f; sc[ms][3] = 0.f;
        }
#pragma unroll
        for (int kc = 0; kc < 4; kc++) {
            const int o0 = kc * 16 + 2 * tg;
            uint2 A0 = *(const uint2*)(g0 + o0);       // (hi, lo)
            uint2 A2 = *(const uint2*)(g0 + o0 + 8);
            uint2 A1 = *(const uint2*)(g1 + o0);
            uint2 A3 = *(const uint2*)(g1 + o0 + 8);
#pragma unroll
            for (int ms = 0; ms < 4; ms++) {
                const uint32_t* f = sFc + (ms * 8 + gr) * GROW;
                uint2 B0 = *(const uint2*)(f + o0);
                uint2 B1 = *(const uint2*)(f + o0 + 8);
                mma_f16(sc[ms], A0.x, A1.x, A2.x, A3.x, B0.x, B1.x);
                mma_f16(sc[ms], A0.x, A1.x, A2.x, A3.x, B0.y, B1.y);
                mma_f16(sc[ms], A0.y, A1.y, A2.y, A3.y, B0.x, B1.x);
            }
        }

        // ---- online softmax (log2 domain), lazy O-rescale ----
        float t0 = NEG_INF, t1 = NEG_INF;
#pragma unroll
        for (int ms = 0; ms < 4; ms++) {
            t0 = fmaxf(t0, fmaxf(sc[ms][0], sc[ms][1]));
            t1 = fmaxf(t1, fmaxf(sc[ms][2], sc[ms][3]));
        }
        t0 = fmaxf(t0, __shfl_xor_sync(0xffffffffu, t0, 1));
        t0 = fmaxf(t0, __shfl_xor_sync(0xffffffffu, t0, 2));
        t1 = fmaxf(t1, __shfl_xor_sync(0xffffffffu, t1, 1));
        t1 = fmaxf(t1, __shfl_xor_sync(0xffffffffu, t1, 2));

        const float mn0 = fmaxf(mrow0, t0);
        const float mn1 = fmaxf(mrow1, t1);
        const bool up = (mn0 != mrow0) || (mn1 != mrow1);
        if (__any_sync(0xffffffffu, up)) {
            const float cr0 = ex2(mrow0 - mn0);
            const float cr1 = ex2(mrow1 - mn1);
            lsum0 *= cr0; lsum1 *= cr1;
#pragma unroll
            for (int dt = 0; dt < 32; dt++) {
                oacc[dt][0] *= cr0; oacc[dt][1] *= cr0;
                oacc[dt][2] *= cr1; oacc[dt][3] *= cr1;
            }
            mrow0 = mn0; mrow1 = mn1;
        }
#pragma unroll
        for (int ms = 0; ms < 4; ms++) {
            sc[ms][0] = ex2(sc[ms][0] - mrow0);
            sc[ms][1] = ex2(sc[ms][1] - mrow0);
            sc[ms][2] = ex2(sc[ms][2] - mrow1);
            sc[ms][3] = ex2(sc[ms][3] - mrow1);
            lsum0 += sc[ms][0] + sc[ms][1];
            lsum1 += sc[ms][2] + sc[ms][3];
        }

        // ---- PV: O += P * H, 1-pass fp16 ----
#pragma unroll
        for (int j = 0; j < 2; j++) {
            const float* cA = sc[2 * j];
            const float* cB = sc[2 * j + 1];
            uint32_t p0 = f16x2(cA[0], cA[1]);
            uint32_t p1 = f16x2(cA[2], cA[3]);
            uint32_t p2 = f16x2(cB[0], cB[1]);
            uint32_t p3 = f16x2(cB[2], cB[3]);
            const uint32_t* hb = sHc + gr * HROW + j * 8;
#pragma unroll
            for (int dt = 0; dt < 32; dt++) {
                const uint32_t* hr = hb + dt * 8 * HROW;
                uint32_t b0 = hr[tg];
                uint32_t b1 = hr[tg + 4];
                mma_f16(oacc[dt], p0, p1, p2, p3, b0, b1);
            }
        }
    }

    // ---- epilogue: l reduce, out = gamma*(O/l) + input, flat [B,N,C] ----
    lsum0 += __shfl_xor_sync(0xffffffffu, lsum0, 1);
    lsum0 += __shfl_xor_sync(0xffffffffu, lsum0, 2);
    lsum1 += __shfl_xor_sync(0xffffffffu, lsum1, 1);
    lsum1 += __shfl_xor_sync(0xffffffffu, lsum1, 2);
    const float inv0 = 1.0f / lsum0;
    const float inv1 = 1.0f / lsum1;
    const float gm = __ldg(gamma_p);

    const int r0 = n0 + w * 16 + gr;
    const int r1 = r0 + 8;
    const size_t base0 = ((size_t)b * N_ + r0) * C_ + tg * 2;
    const size_t base1 = ((size_t)b * N_ + r1) * C_ + tg * 2;
#pragma unroll
    for (int dt = 0; dt < 32; dt++) {
        float2 iv0 = *(const float2*)(input + base0 + dt * 8);
        float2 iv1 = *(const float2*)(input + base1 + dt * 8);
        float2 ov0, ov1;
        ov0.x = fmaf(gm, oacc[dt][0] * inv0, iv0.x);
        ov0.y = fmaf(gm, oacc[dt][1] * inv0, iv0.y);
        ov1.x = fmaf(gm, oacc[dt][2] * inv1, iv1.x);
        ov1.y = fmaf(gm, oacc[dt][3] * inv1, iv1.y);
        *(float2*)(out + base0 + dt * 8) = ov0;
        *(float2*)(out + base1 + dt * 8) = ov1;
    }
}

// ---------------------------------------------------------------------------
extern "C" void kernel_launch(void* const* d_in, const int* in_sizes, int n_in,
                              void* d_out, int out_size) {
    (void)in_sizes; (void)n_in; (void)out_size;
    const float* input = (const float*)d_in[0];
    const float* feat  = (const float*)d_in[1];   // nms_feat
    const float* WF    = (const float*)d_in[2];
    const float* WG    = (const float*)d_in[3];
    const float* WH    = (const float*)d_in[4];
    const float* gamma = (const float*)d_in[5];
    float* out = (float*)d_out;

    cudaFuncSetAttribute(attn_kernel,
                         cudaFuncAttributeMaxDynamicSharedMemorySize, SMEMB);

    proj_kernel<<<dim3(N_ / 128, 12, B_), 128>>>(feat, WF, WG, WH);
    attn_kernel<<<dim3(N_ / 128, B_), 256, SMEMB>>>(input, gamma, out);
}

// round 7
// speedup vs baseline: 6.4802x; 1.1016x over previous
#include <cuda_runtime.h>
#include <cuda_fp16.h>
#include <cstdint>

#define B_ 8
#define C_ 256
#define N_ 4096
#define K_ 64
#define MT 32
#define LOG2E 1.4426950408889634f

// Scratch (fp16 hi/lo packed). F/G rows: 64 u32 = [hi-pair0, lo-pair0, hi-pair1, ...]
// pair p = (k=2p, k=2p+1). H: fp16 single, TRANSPOSED [b][d][n].
__device__ uint32_t g_F[(size_t)B_ * N_ * 64];
__device__ uint32_t g_G[(size_t)B_ * N_ * 64];     // pre-scaled by log2(e)
__device__ uint16_t g_H[(size_t)B_ * C_ * N_];

// ---------------- helpers ----------------
__device__ __forceinline__ uint32_t f16x2(float lo, float hi) {
    uint32_t r;  // d<15:0>=cvt(b)=lo, d<31:16>=cvt(a)=hi
    asm("cvt.rn.f16x2.f32 %0, %1, %2;" : "=r"(r) : "f"(hi), "f"(lo));
    return r;
}
__device__ __forceinline__ float f16lo(uint32_t p) {
    return __half2float(__ushort_as_half((unsigned short)(p & 0xffffu)));
}
__device__ __forceinline__ float f16hi(uint32_t p) {
    return __half2float(__ushort_as_half((unsigned short)(p >> 16)));
}
__device__ __forceinline__ float ex2(float x) {
    float r; asm("ex2.approx.f32 %0, %1;" : "=f"(r) : "f"(x)); return r;
}
__device__ __forceinline__ void mma_f16(float* c,
    uint32_t a0, uint32_t a1, uint32_t a2, uint32_t a3,
    uint32_t b0, uint32_t b1) {
    asm volatile("mma.sync.aligned.m16n8k16.row.col.f32.f16.f16.f32 "
        "{%0,%1,%2,%3},{%4,%5,%6,%7},{%8,%9},{%0,%1,%2,%3};"
        : "+f"(c[0]), "+f"(c[1]), "+f"(c[2]), "+f"(c[3])
        : "r"(a0), "r"(a1), "r"(a2), "r"(a3), "r"(b0), "r"(b1));
}
__device__ __forceinline__ void cp16(uint32_t dst, const void* src) {
    asm volatile("cp.async.cg.shared.global [%0], [%1], 16;" :: "r"(dst), "l"(src));
}
__device__ __forceinline__ void cp_commit() { asm volatile("cp.async.commit_group;"); }
__device__ __forceinline__ void cp_wait0()  { asm volatile("cp.async.wait_group 0;"); }
__device__ __forceinline__ unsigned long long ffma2(unsigned long long a,
                                                    unsigned long long b,
                                                    unsigned long long c) {
    unsigned long long d;
    asm("fma.rn.f32x2 %0, %1, %2, %3;" : "=l"(d) : "l"(a), "l"(b), "l"(c));
    return d;
}
__device__ __forceinline__ unsigned long long pack2(float x) {
    unsigned long long r;
    unsigned int xi = __float_as_uint(x);
    asm("mov.b64 %0, {%1, %1};" : "=l"(r) : "r"(xi));
    return r;
}
__device__ __forceinline__ unsigned long long pack2v(float a, float b) {
    unsigned long long r;
    asm("mov.b64 %0, {%1, %2};" : "=l"(r)
        : "r"(__float_as_uint(a)), "r"(__float_as_uint(b)));
    return r;
}
__device__ __forceinline__ float2 unpack2(unsigned long long v) {
    unsigned int lo, hi;
    asm("mov.b64 {%0, %1}, %2;" : "=r"(lo), "=r"(hi) : "l"(v));
    return make_float2(__uint_as_float(lo), __uint_as_float(hi));
}

// ---------------------------------------------------------------------------
// Projection, restructured: thread computes 8 rows x 4 n.
// Feat loaded as coalesced float4; W via 2 broadcast LDS.128 per channel
// (was 8). Accumulation order per output element identical to the previous
// version -> g_F/g_G/g_H bit-identical.
// rg 0-1 -> F (fp16 hi/lo), 2-3 -> G (scaled by log2e, hi/lo),
// 4-11 -> H (fp16, transposed [d][n]). Block: 128 n x 32 rows.
// ---------------------------------------------------------------------------
__global__ __launch_bounds__(128) void proj_kernel(
    const float* __restrict__ feat,
    const float* __restrict__ WF,
    const float* __restrict__ WG,
    const float* __restrict__ WH)
{
    __shared__ float sW[256 * 36];
    const int rg = blockIdx.y;
    const int b  = blockIdx.z;

    const float* W;
    int r0, mode;                      // 0=F, 1=G, 2=H
    if (rg < 2)      { W = WF; r0 = rg * 32;       mode = 0; }
    else if (rg < 4) { W = WG; r0 = (rg - 2) * 32; mode = 1; }
    else             { W = WH; r0 = (rg - 4) * 32; mode = 2; }

    // stage W[r0..r0+31][0..255] transposed: sW[c*36 + r]
    for (int i = threadIdx.x; i < 32 * 256; i += 128) {
        int r = i >> 8, c = i & 255;
        sW[c * 36 + r] = W[(size_t)(r0 + r) * C_ + c];
    }
    __syncthreads();

    const int q  = threadIdx.x & 31;    // n-quad
    const int rh = threadIdx.x >> 5;    // row-half (8 rows)
    const int n  = blockIdx.x * 128 + q * 4;
    const float* fb = feat + (size_t)b * C_ * N_;
    const float* wp = sW + rh * 8;

    unsigned long long acc[8][2];       // [row j][n-pair]
#pragma unroll
    for (int j = 0; j < 8; j++) { acc[j][0] = 0ULL; acc[j][1] = 0ULL; }

#pragma unroll 4
    for (int c = 0; c < C_; c++) {
        float4 x = __ldg((const float4*)(fb + (size_t)c * N_ + n));
        unsigned long long x01 = pack2v(x.x, x.y);
        unsigned long long x23 = pack2v(x.z, x.w);
        float4 w0 = *(const float4*)(wp + c * 36);       // broadcast
        float4 w1 = *(const float4*)(wp + c * 36 + 4);   // broadcast
#pragma unroll
        for (int j = 0; j < 8; j++) {
            float wj = (j < 4) ? ((const float*)&w0)[j] : ((const float*)&w1)[j - 4];
            unsigned long long w2 = pack2(wj);
            acc[j][0] = ffma2(x01, w2, acc[j][0]);
            acc[j][1] = ffma2(x23, w2, acc[j][1]);
        }
    }

    // unpack: val[j][e] = output for row (r0+rh*8+j), column n+e
    float val[8][4];
#pragma unroll
    for (int j = 0; j < 8; j++) {
        float2 a = unpack2(acc[j][0]);
        float2 c2 = unpack2(acc[j][1]);
        val[j][0] = a.x; val[j][1] = a.y; val[j][2] = c2.x; val[j][3] = c2.y;
    }

    if (mode == 2) {
        // H: g_H[b][d][n..n+3], d = r0 + rh*8 + j
#pragma unroll
        for (int j = 0; j < 8; j++) {
            const int d = r0 + rh * 8 + j;
            uint2 o;
            o.x = f16x2(val[j][0], val[j][1]);
            o.y = f16x2(val[j][2], val[j][3]);
            *(uint2*)(g_H + ((size_t)b * C_ + d) * N_ + n) = o;
        }
    } else {
        const float scale = (mode == 1) ? LOG2E : 1.0f;
        uint32_t* dstb = (mode == 1 ? g_G : g_F);
#pragma unroll
        for (int e = 0; e < 4; e++) {
            // row n+e: k values j=0..7 -> pairs jp=0..3, interleaved [hi,lo]
            uint32_t u[8];
#pragma unroll
            for (int jp = 0; jp < 4; jp++) {
                float x0 = val[2 * jp][e] * scale;
                float x1 = val[2 * jp + 1][e] * scale;
                uint32_t hi2 = f16x2(x0, x1);
                uint32_t lo2 = f16x2(x0 - f16lo(hi2), x1 - f16hi(hi2));
                u[2 * jp] = hi2; u[2 * jp + 1] = lo2;
            }
            uint32_t* dst = dstb + ((size_t)b * N_ + n + e) * 64 + r0 + rh * 8;
            uint4 U0; U0.x = u[0]; U0.y = u[1]; U0.z = u[2]; U0.w = u[3];
            uint4 U1; U1.x = u[4]; U1.y = u[5]; U1.z = u[6]; U1.w = u[7];
            *(uint4*)dst = U0;
            *(uint4*)(dst + 4) = U1;
        }
    }
}

// ---------------------------------------------------------------------------
// fp16 hi/lo flash attention (UNCHANGED from round 5 — passed at 9.2e-5).
// Block = 128 q-rows, 8 warps, warp = 16 rows x 256 d.
// m-tiles of 32, cp.async double-buffered.
// S = 3-pass fp16 (Gh.Fh + Gh.Fl + Gl.Fh), m16n8k16 -> ~21-bit logits.
// PV = 1-pass (P fp16, H fp16).
// ---------------------------------------------------------------------------
#define GROW 72                          // u32 per G/F smem row (64 + pad)
#define HROW 20                          // u32 per H smem row (16 + pad)
#define SG  0
#define SF  (128 * GROW)
#define FPL (MT * GROW)                  // 2304
#define SH  (SF + 2 * FPL)
#define HPL (C_ * HROW)                  // 5120
#define SMEMU (SH + 2 * HPL)             // 24064 u32
#define SMEMB (SMEMU * 4)                // 96256 B

__global__ __launch_bounds__(256, 1) void attn_kernel(
    const float* __restrict__ input,
    const float* __restrict__ gamma_p,
    float* __restrict__ out)
{
    extern __shared__ uint32_t sm[];
    uint32_t smu;
    asm("{ .reg .u64 t; cvta.to.shared.u64 t, %1; cvt.u32.u64 %0, t; }"
        : "=r"(smu) : "l"(sm));

    const int tid  = threadIdx.x;
    const int lane = tid & 31;
    const int w    = tid >> 5;
    const int gr   = lane >> 2;
    const int tg   = lane & 3;
    const int n0   = blockIdx.x * 128;
    const int b    = blockIdx.y;

    const uint32_t* FG = g_F + (size_t)b * N_ * 64;
    const uint32_t* HG = (const uint32_t*)(g_H + (size_t)b * C_ * N_); // [d][n] fp16

    // stage G tile (128 rows x 64 u32) once via cp.async
    {
        const uint32_t* GG = g_G + ((size_t)b * N_ + n0) * 64;
        for (int i = tid; i < 128 * 16; i += 256) {
            int r = i >> 4, ch = i & 15;
            cp16(smu + (SG + r * GROW + ch * 4) * 4, GG + r * 64 + ch * 4);
        }
    }
    // prefetch m-tile 0 into buf 0
    {
        for (int i = tid; i < 512; i += 256) {
            int r = i >> 4, ch = i & 15;
            cp16(smu + (SF + r * GROW + ch * 4) * 4, FG + (size_t)r * 64 + ch * 4);
        }
        for (int i = tid; i < 1024; i += 256) {
            int r = i >> 2, ch = i & 3;   // r = d 0..255
            cp16(smu + (SH + r * HROW + ch * 4) * 4, HG + (size_t)r * 2048 + ch * 4);
        }
        cp_commit();
    }

    float oacc[32][4];
#pragma unroll
    for (int i = 0; i < 32; i++) {
        oacc[i][0] = 0.f; oacc[i][1] = 0.f; oacc[i][2] = 0.f; oacc[i][3] = 0.f;
    }
    const float NEG_INF = __int_as_float(0xff800000);
    float mrow0 = NEG_INF, mrow1 = NEG_INF, lsum0 = 0.f, lsum1 = 0.f;

    const uint32_t* g0 = sm + SG + (w * 16 + gr) * GROW;
    const uint32_t* g1 = g0 + 8 * GROW;

#pragma unroll 1
    for (int t = 0; t < N_ / MT; t++) {
        cp_wait0();
        __syncthreads();

        const int cur = t & 1;
        if (t + 1 < N_ / MT) {
            const int m0n = (t + 1) * MT;
            const int nb = cur ^ 1;
            for (int i = tid; i < 512; i += 256) {
                int r = i >> 4, ch = i & 15;
                cp16(smu + (SF + nb * FPL + r * GROW + ch * 4) * 4,
                     FG + (size_t)(m0n + r) * 64 + ch * 4);
            }
            for (int i = tid; i < 1024; i += 256) {
                int r = i >> 2, ch = i & 3;
                cp16(smu + (SH + nb * HPL + r * HROW + ch * 4) * 4,
                     HG + (size_t)r * 2048 + m0n / 2 + ch * 4);
            }
            cp_commit();
        }

        const uint32_t* sFc = sm + SF + cur * FPL;
        const uint32_t* sHc = sm + SH + cur * HPL;

        // ---- S tile: sc[ms] = 16n x 8m C-frags, 3-pass fp16 k16 ----
        float sc[4][4];
#pragma unroll
        for (int ms = 0; ms < 4; ms++) {
            sc[ms][0] = 0.f; sc[ms][1] = 0.f; sc[ms][2] = 0.f; sc[ms][3] = 0.f;
        }
#pragma unroll
        for (int kc = 0; kc < 4; kc++) {
            const int o0 = kc * 16 + 2 * tg;
            uint2 A0 = *(const uint2*)(g0 + o0);       // (hi, lo)
            uint2 A2 = *(const uint2*)(g0 + o0 + 8);
            uint2 A1 = *(const uint2*)(g1 + o0);
            uint2 A3 = *(const uint2*)(g1 + o0 + 8);
#pragma unroll
            for (int ms = 0; ms < 4; ms++) {
                const uint32_t* f = sFc + (ms * 8 + gr) * GROW;
                uint2 B0 = *(const uint2*)(f + o0);
                uint2 B1 = *(const uint2*)(f + o0 + 8);
                mma_f16(sc[ms], A0.x, A1.x, A2.x, A3.x, B0.x, B1.x);
                mma_f16(sc[ms], A0.x, A1.x, A2.x, A3.x, B0.y, B1.y);
                mma_f16(sc[ms], A0.y, A1.y, A2.y, A3.y, B0.x, B1.x);
            }
        }

        // ---- online softmax (log2 domain), lazy O-rescale ----
        float t0 = NEG_INF, t1 = NEG_INF;
#pragma unroll
        for (int ms = 0; ms < 4; ms++) {
            t0 = fmaxf(t0, fmaxf(sc[ms][0], sc[ms][1]));
            t1 = fmaxf(t1, fmaxf(sc[ms][2], sc[ms][3]));
        }
        t0 = fmaxf(t0, __shfl_xor_sync(0xffffffffu, t0, 1));
        t0 = fmaxf(t0, __shfl_xor_sync(0xffffffffu, t0, 2));
        t1 = fmaxf(t1, __shfl_xor_sync(0xffffffffu, t1, 1));
        t1 = fmaxf(t1, __shfl_xor_sync(0xffffffffu, t1, 2));

        const float mn0 = fmaxf(mrow0, t0);
        const float mn1 = fmaxf(mrow1, t1);
        const bool up = (mn0 != mrow0) || (mn1 != mrow1);
        if (__any_sync(0xffffffffu, up)) {
            const float cr0 = ex2(mrow0 - mn0);
            const float cr1 = ex2(mrow1 - mn1);
            lsum0 *= cr0; lsum1 *= cr1;
#pragma unroll
            for (int dt = 0; dt < 32; dt++) {
                oacc[dt][0] *= cr0; oacc[dt][1] *= cr0;
                oacc[dt][2] *= cr1; oacc[dt][3] *= cr1;
            }
            mrow0 = mn0; mrow1 = mn1;
        }
#pragma unroll
        for (int ms = 0; ms < 4; ms++) {
            sc[ms][0] = ex2(sc[ms][0] - mrow0);
            sc[ms][1] = ex2(sc[ms][1] - mrow0);
            sc[ms][2] = ex2(sc[ms][2] - mrow1);
            sc[ms][3] = ex2(sc[ms][3] - mrow1);
            lsum0 += sc[ms][0] + sc[ms][1];
            lsum1 += sc[ms][2] + sc[ms][3];
        }

        // ---- PV: O += P * H, 1-pass fp16 ----
#pragma unroll
        for (int j = 0; j < 2; j++) {
            const float* cA = sc[2 * j];
            const float* cB = sc[2 * j + 1];
            uint32_t p0 = f16x2(cA[0], cA[1]);
            uint32_t p1 = f16x2(cA[2], cA[3]);
            uint32_t p2 = f16x2(cB[0], cB[1]);
            uint32_t p3 = f16x2(cB[2], cB[3]);
            const uint32_t* hb = sHc + gr * HROW + j * 8;
#pragma unroll
            for (int dt = 0; dt < 32; dt++) {
                const uint32_t* hr = hb + dt * 8 * HROW;
                uint32_t b0 = hr[tg];
                uint32_t b1 = hr[tg + 4];
                mma_f16(oacc[dt], p0, p1, p2, p3, b0, b1);
            }
        }
    }

    // ---- epilogue: l reduce, out = gamma*(O/l) + input, flat [B,N,C] ----
    lsum0 += __shfl_xor_sync(0xffffffffu, lsum0, 1);
    lsum0 += __shfl_xor_sync(0xffffffffu, lsum0, 2);
    lsum1 += __shfl_xor_sync(0xffffffffu, lsum1, 1);
    lsum1 += __shfl_xor_sync(0xffffffffu, lsum1, 2);
    const float inv0 = 1.0f / lsum0;
    const float inv1 = 1.0f / lsum1;
    const float gm = __ldg(gamma_p);

    const int r0 = n0 + w * 16 + gr;
    const int r1 = r0 + 8;
    const size_t base0 = ((size_t)b * N_ + r0) * C_ + tg * 2;
    const size_t base1 = ((size_t)b * N_ + r1) * C_ + tg * 2;
#pragma unroll
    for (int dt = 0; dt < 32; dt++) {
        float2 iv0 = *(const float2*)(input + base0 + dt * 8);
        float2 iv1 = *(const float2*)(input + base1 + dt * 8);
        float2 ov0, ov1;
        ov0.x = fmaf(gm, oacc[dt][0] * inv0, iv0.x);
        ov0.y = fmaf(gm, oacc[dt][1] * inv0, iv0.y);
        ov1.x = fmaf(gm, oacc[dt][2] * inv1, iv1.x);
        ov1.y = fmaf(gm, oacc[dt][3] * inv1, iv1.y);
        *(float2*)(out + base0 + dt * 8) = ov0;
        *(float2*)(out + base1 + dt * 8) = ov1;
    }
}

// ---------------------------------------------------------------------------
extern "C" void kernel_launch(void* const* d_in, const int* in_sizes, int n_in,
                              void* d_out, int out_size) {
    (void)in_sizes; (void)n_in; (void)out_size;
    const float* input = (const float*)d_in[0];
    const float* feat  = (const float*)d_in[1];   // nms_feat
    const float* WF    = (const float*)d_in[2];
    const float* WG    = (const float*)d_in[3];
    const float* WH    = (const float*)d_in[4];
    const float* gamma = (const float*)d_in[5];
    float* out = (float*)d_out;

    cudaFuncSetAttribute(attn_kernel,
                         cudaFuncAttributeMaxDynamicSharedMemorySize, SMEMB);

    proj_kernel<<<dim3(N_ / 128, 12, B_), 128>>>(feat, WF, WG, WH);
    attn_kernel<<<dim3(N_ / 128, B_), 256, SMEMB>>>(input, gamma, out);
}